// round 1
// baseline (speedup 1.0000x reference)
#include <cuda_runtime.h>
#include <cuda_bf16.h>

// Problem constants
#define B_   4
#define L_   2048
#define D_   1024
#define H_   16
#define HD_  64
#define E_   3072          // 3*D
#define M_   (B_ * L_)     // 8192 rows

// Scratch (device globals; no allocation allowed)
__device__ float g_qkv[(size_t)M_ * E_];    // [8192, 3072]
__device__ float g_att[(size_t)M_ * D_];    // [8192, 1024]

// ---------------------------------------------------------------------------
// Tiled SGEMM with fused bias: C[M,N] = A[M,K] @ B[K,N] + bias[N]
// BM=128, BN=64, BK=16, 256 threads, each computes 8x4.
// ---------------------------------------------------------------------------
template <int BM, int BN, int BK, int TM, int TN>
__global__ __launch_bounds__(256) void sgemm_bias_kernel(
    const float* __restrict__ A, const float* __restrict__ Bm,
    const float* __restrict__ bias, float* __restrict__ C,
    int M, int N, int K)
{
    __shared__ float As[BK][BM];
    __shared__ float Bs[BK][BN];

    const int tid  = threadIdx.x;                 // 0..255
    const int tcol = tid % (BN / TN);             // 0..15
    const int trow = tid / (BN / TN);             // 0..15
    const int row0 = blockIdx.y * BM;
    const int col0 = blockIdx.x * BN;

    float acc[TM][TN];
    #pragma unroll
    for (int i = 0; i < TM; i++)
        #pragma unroll
        for (int j = 0; j < TN; j++)
            acc[i][j] = 0.f;

    for (int k0 = 0; k0 < K; k0 += BK) {
        // A tile: BM x BK, stored transposed As[k][m]
        #pragma unroll
        for (int i = tid; i < BM * BK; i += 256) {
            int m = i / BK, k = i % BK;
            As[k][m] = A[(size_t)(row0 + m) * K + k0 + k];
        }
        // B tile: BK x BN
        #pragma unroll
        for (int i = tid; i < BK * BN; i += 256) {
            int k = i / BN, n = i % BN;
            Bs[k][n] = Bm[(size_t)(k0 + k) * N + col0 + n];
        }
        __syncthreads();

        #pragma unroll
        for (int k = 0; k < BK; k++) {
            float ra[TM], rb[TN];
            #pragma unroll
            for (int i = 0; i < TM; i++) ra[i] = As[k][trow * TM + i];
            #pragma unroll
            for (int j = 0; j < TN; j++) rb[j] = Bs[k][tcol * TN + j];
            #pragma unroll
            for (int i = 0; i < TM; i++)
                #pragma unroll
                for (int j = 0; j < TN; j++)
                    acc[i][j] += ra[i] * rb[j];
        }
        __syncthreads();
    }

    #pragma unroll
    for (int i = 0; i < TM; i++) {
        int r = row0 + trow * TM + i;
        #pragma unroll
        for (int j = 0; j < TN; j++) {
            int c = col0 + tcol * TN + j;
            C[(size_t)r * N + c] = acc[i][j] + bias[c];
        }
    }
}

// ---------------------------------------------------------------------------
// Flash attention (causal), fp32, one q-row per thread.
// grid: (L/BQ, H, B), block: BQ=128 threads. K/V staged in smem tiles of TK=32.
// qkv layout: [B*L, 3D]; q at col h*64, k at D + h*64, v at 2D + h*64.
// Output g_att: [B*L, D] at col h*64.
// ---------------------------------------------------------------------------
#define BQ_ 128
#define TK_ 32

__global__ __launch_bounds__(BQ_) void attn_kernel(
    const float* __restrict__ qkv, float* __restrict__ out)
{
    const int qt = blockIdx.x;
    const int h  = blockIdx.y;
    const int b  = blockIdx.z;
    const int tid = threadIdx.x;

    const int q_idx = qt * BQ_ + tid;  // local sequence index of this thread's row
    const size_t qoff = (size_t)(b * L_ + q_idx) * E_ + h * HD_;

    float q[HD_], o[HD_];
    #pragma unroll
    for (int d = 0; d < HD_; d++) { q[d] = qkv[qoff + d]; o[d] = 0.f; }

    float m = -1e30f, l = 0.f;
    const float scale = 0.125f;  // 1/sqrt(64)

    __shared__ float Ks[TK_][HD_];
    __shared__ float Vs[TK_][HD_];

    const int kmax = qt * BQ_ + BQ_ - 1;  // last kv index any thread in block needs

    for (int kt = 0; kt <= kmax; kt += TK_) {
        // Cooperative load of K and V tiles
        #pragma unroll
        for (int i = tid; i < TK_ * HD_; i += BQ_) {
            int j = i / HD_, d = i % HD_;
            size_t rk = (size_t)(b * L_ + kt + j) * E_;
            Ks[j][d] = qkv[rk + D_ + h * HD_ + d];
            Vs[j][d] = qkv[rk + 2 * D_ + h * HD_ + d];
        }
        __syncthreads();

        float s[TK_];
        float tmax = -1e30f;
        #pragma unroll 4
        for (int j = 0; j < TK_; j++) {
            if (kt + j <= q_idx) {
                float acc = 0.f;
                #pragma unroll
                for (int d = 0; d < HD_; d++) acc += q[d] * Ks[j][d];
                s[j] = acc * scale;
                tmax = fmaxf(tmax, s[j]);
            } else {
                s[j] = -1e30f;
            }
        }

        float mnew = fmaxf(m, tmax);
        float corr = __expf(m - mnew);
        l *= corr;
        #pragma unroll
        for (int d = 0; d < HD_; d++) o[d] *= corr;

        #pragma unroll 4
        for (int j = 0; j < TK_; j++) {
            float p = __expf(s[j] - mnew);  // 0 for masked entries
            l += p;
            #pragma unroll
            for (int d = 0; d < HD_; d++) o[d] += p * Vs[j][d];
        }
        m = mnew;
        __syncthreads();
    }

    const float inv = 1.0f / l;
    const size_t ooff = (size_t)(b * L_ + q_idx) * D_ + h * HD_;
    #pragma unroll
    for (int d = 0; d < HD_; d++) out[ooff + d] = o[d] * inv;
}

// ---------------------------------------------------------------------------
extern "C" void kernel_launch(void* const* d_in, const int* in_sizes, int n_in,
                              void* d_out, int out_size)
{
    const float* x     = (const float*)d_in[0];  // [4,2048,1024]
    const float* w_in  = (const float*)d_in[1];  // [1024,3072]
    const float* b_in  = (const float*)d_in[2];  // [3072]
    const float* w_out = (const float*)d_in[3];  // [1024,1024]
    const float* b_out = (const float*)d_in[4];  // [1024]
    float* y = (float*)d_out;                    // [4,2048,1024]

    float* qkv = nullptr;
    float* att = nullptr;
    cudaGetSymbolAddress((void**)&qkv, g_qkv);
    cudaGetSymbolAddress((void**)&att, g_att);

    // 1) QKV projection: [8192,1024] @ [1024,3072] + b_in
    {
        dim3 grid(E_ / 64, M_ / 128);
        sgemm_bias_kernel<128, 64, 16, 8, 4><<<grid, 256>>>(
            x, w_in, b_in, qkv, M_, E_, D_);
    }

    // 2) Causal flash attention per (b, h)
    {
        dim3 grid(L_ / BQ_, H_, B_);
        attn_kernel<<<grid, BQ_>>>(qkv, att);
    }

    // 3) Output projection: [8192,1024] @ [1024,1024] + b_out
    {
        dim3 grid(D_ / 64, M_ / 128);
        sgemm_bias_kernel<128, 64, 16, 8, 4><<<grid, 256>>>(
            att, w_out, b_out, y, M_, D_, D_);
    }
}

// round 3
// speedup vs baseline: 1.6448x; 1.6448x over previous
#include <cuda_runtime.h>
#include <cuda_bf16.h>
#include <cstdint>

// ---------------------------------------------------------------------------
// Problem constants
// ---------------------------------------------------------------------------
#define B_   4
#define L_   2048
#define D_   1024
#define H_   16
#define HD_  64
#define E_   3072          // 3*D
#define M_   (B_ * L_)     // 8192 rows

// ---------------------------------------------------------------------------
// Scratch (device globals; no allocation allowed)
// ---------------------------------------------------------------------------
__device__ float          g_qkv[(size_t)M_ * E_];      // [8192, 3072] fp32 (attention input)
__device__ __nv_bfloat16  g_xh[(size_t)M_ * D_];       // x hi/lo
__device__ __nv_bfloat16  g_xl[(size_t)M_ * D_];
__device__ __nv_bfloat16  g_winT_h[(size_t)E_ * D_];   // w_in^T [3072,1024]
__device__ __nv_bfloat16  g_winT_l[(size_t)E_ * D_];
__device__ __nv_bfloat16  g_woutT_h[(size_t)D_ * D_];  // w_out^T [1024,1024]
__device__ __nv_bfloat16  g_woutT_l[(size_t)D_ * D_];
__device__ __nv_bfloat16  g_atth[(size_t)M_ * D_];     // attention out hi/lo
__device__ __nv_bfloat16  g_attl[(size_t)M_ * D_];

// ---------------------------------------------------------------------------
// Helpers
// ---------------------------------------------------------------------------
__device__ __forceinline__ uint32_t smem_u32(const void* p) {
    uint32_t a;
    asm("{ .reg .u64 t; cvta.to.shared.u64 t, %1; cvt.u32.u64 %0, t; }" : "=r"(a) : "l"(p));
    return a;
}

#define CP_ASYNC16(saddr, gptr) \
    asm volatile("cp.async.cg.shared.global [%0], [%1], 16;" :: "r"(saddr), "l"(gptr))
#define CP_COMMIT() asm volatile("cp.async.commit_group;" ::: "memory")
#define CP_WAIT(n)  asm volatile("cp.async.wait_group %0;" :: "n"(n) : "memory")

__device__ __forceinline__ void mma_bf16(float& c0, float& c1, float& c2, float& c3,
                                         uint32_t a0, uint32_t a1, uint32_t a2, uint32_t a3,
                                         uint32_t b0, uint32_t b1) {
    asm volatile(
        "mma.sync.aligned.m16n8k16.row.col.f32.bf16.bf16.f32 "
        "{%0,%1,%2,%3}, {%4,%5,%6,%7}, {%8,%9}, {%0,%1,%2,%3};"
        : "+f"(c0), "+f"(c1), "+f"(c2), "+f"(c3)
        : "r"(a0), "r"(a1), "r"(a2), "r"(a3), "r"(b0), "r"(b1));
}

// ---------------------------------------------------------------------------
// Prep kernels
// ---------------------------------------------------------------------------
__global__ void convert_split_kernel(const float* __restrict__ src,
                                     __nv_bfloat16* __restrict__ hi,
                                     __nv_bfloat16* __restrict__ lo, int n)
{
    for (int i = blockIdx.x * blockDim.x + threadIdx.x; i < n; i += gridDim.x * blockDim.x) {
        float v = src[i];
        __nv_bfloat16 h = __float2bfloat16(v);
        hi[i] = h;
        lo[i] = __float2bfloat16(v - __bfloat162float(h));
    }
}

// src [K, N] row-major  ->  dst hi/lo [N, K] bf16
__global__ void transpose_split_kernel(const float* __restrict__ src,
                                       __nv_bfloat16* __restrict__ hi,
                                       __nv_bfloat16* __restrict__ lo, int K, int N)
{
    __shared__ float tile[32][33];
    int n0 = blockIdx.x * 32, k0 = blockIdx.y * 32;
    int tx = threadIdx.x, ty = threadIdx.y;
    tile[ty][tx] = src[(size_t)(k0 + ty) * N + n0 + tx];
    __syncthreads();
    float v = tile[tx][ty];
    __nv_bfloat16 h = __float2bfloat16(v);
    size_t o = (size_t)(n0 + ty) * K + k0 + tx;
    hi[o] = h;
    lo[o] = __float2bfloat16(v - __bfloat162float(h));
}

// ---------------------------------------------------------------------------
// mma.sync bf16 split GEMM:
//   C[M,N] = (Ah+Al)[M,K] @ (Bh+Bl)[N,K]^T + bias[N]   (fp32 out)
// Block 256 thr (8 warps, 2x4), tile 128x128x32, cp.async double-buffered.
// Smem rows padded: 32 bf16 + 8 pad = 80B/row -> conflict-free frag loads.
// ---------------------------------------------------------------------------
#define BKG 32
#define ROWB 80                      // padded row bytes (32 bf16 + 16B pad)
#define MATB (128 * ROWB)            // 10240 bytes per matrix tile
#define STAGEB (4 * MATB)            // Ah, Al, Bh, Bl
#define SMEMB (2 * STAGEB)           // 81920

__global__ __launch_bounds__(256, 2) void gemm_mma_kernel(
    const __nv_bfloat16* __restrict__ Ah, const __nv_bfloat16* __restrict__ Al,
    const __nv_bfloat16* __restrict__ Bh, const __nv_bfloat16* __restrict__ Bl,
    const float* __restrict__ bias, float* __restrict__ C,
    int M, int N, int K)
{
    extern __shared__ char sm[];
    const int tid  = threadIdx.x;
    const int lane = tid & 31;
    const int wid  = tid >> 5;
    const int wm   = wid & 1;           // 2 warps along M (64 rows each)
    const int wn   = wid >> 1;          // 4 warps along N (32 cols each)
    const int row0 = blockIdx.y * 128;
    const int col0 = blockIdx.x * 128;
    const uint32_t smem_base = smem_u32(sm);

    float acc[4][4][4];
    #pragma unroll
    for (int i = 0; i < 4; i++)
        #pragma unroll
        for (int j = 0; j < 4; j++)
            #pragma unroll
            for (int c = 0; c < 4; c++) acc[i][j][c] = 0.f;

    const int nk = K / BKG;

    // tile loader: 512 16B-chunks per matrix, 2 per thread
    auto load_stage = [&](int i) {
        const int k0 = i * BKG;
        const uint32_t sbase = smem_base + (i & 1) * STAGEB;
        #pragma unroll
        for (int t = 0; t < 2; t++) {
            int c = tid + t * 256;
            int r = c >> 2, c8 = c & 3;            // row 0..127, 16B chunk 0..3
            uint32_t so = r * ROWB + c8 * 16;
            size_t ga = (size_t)(row0 + r) * K + k0 + c8 * 8;
            size_t gb = (size_t)(col0 + r) * K + k0 + c8 * 8;
            CP_ASYNC16(sbase + 0 * MATB + so, Ah + ga);
            CP_ASYNC16(sbase + 1 * MATB + so, Al + ga);
            CP_ASYNC16(sbase + 2 * MATB + so, Bh + gb);
            CP_ASYNC16(sbase + 3 * MATB + so, Bl + gb);
        }
        CP_COMMIT();
    };

    load_stage(0);

    const int arow = (lane >> 2);
    const int acol = (lane & 3) * 2;

    for (int i = 0; i < nk; i++) {
        if (i + 1 < nk) load_stage(i + 1);
        if (i + 1 < nk) { CP_WAIT(1); } else { CP_WAIT(0); }
        __syncthreads();

        const char* st = sm + (i & 1) * STAGEB;
        const char* pA[2] = { st + 0 * MATB, st + 1 * MATB };
        const char* pB[2] = { st + 2 * MATB, st + 3 * MATB };

        #pragma unroll
        for (int kk = 0; kk < 2; kk++) {          // two k16 halves
            const int colb = (kk * 16 + acol) * 2; // byte col offset
            // products: 0 = Ah*Bh, 1 = Ah*Bl, 2 = Al*Bh
            #pragma unroll
            for (int p = 0; p < 3; p++) {
                const char* Abase = pA[p == 2 ? 1 : 0];
                const char* Bbase = pB[p == 1 ? 1 : 0];
                uint32_t afr[4][4], bfr[4][2];
                #pragma unroll
                for (int im = 0; im < 4; im++) {
                    int r = wm * 64 + im * 16 + arow;
                    afr[im][0] = *(const uint32_t*)(Abase + r * ROWB + colb);
                    afr[im][1] = *(const uint32_t*)(Abase + (r + 8) * ROWB + colb);
                    afr[im][2] = *(const uint32_t*)(Abase + r * ROWB + colb + 16);
                    afr[im][3] = *(const uint32_t*)(Abase + (r + 8) * ROWB + colb + 16);
                }
                #pragma unroll
                for (int in = 0; in < 4; in++) {
                    int n = wn * 32 + in * 8 + arow;
                    bfr[in][0] = *(const uint32_t*)(Bbase + n * ROWB + colb);
                    bfr[in][1] = *(const uint32_t*)(Bbase + n * ROWB + colb + 16);
                }
                #pragma unroll
                for (int im = 0; im < 4; im++)
                    #pragma unroll
                    for (int in = 0; in < 4; in++)
                        mma_bf16(acc[im][in][0], acc[im][in][1], acc[im][in][2], acc[im][in][3],
                                 afr[im][0], afr[im][1], afr[im][2], afr[im][3],
                                 bfr[in][0], bfr[in][1]);
            }
        }
        __syncthreads();
    }

    // epilogue: D frag: c0,c1 at (row=lane/4, col=(lane%4)*2), c2,c3 at row+8
    #pragma unroll
    for (int im = 0; im < 4; im++) {
        int r = row0 + wm * 64 + im * 16 + arow;
        #pragma unroll
        for (int in = 0; in < 4; in++) {
            int cc = col0 + wn * 32 + in * 8 + acol;
            float2 b0 = *(const float2*)(bias + cc);
            float2 v0 = { acc[im][in][0] + b0.x, acc[im][in][1] + b0.y };
            float2 v1 = { acc[im][in][2] + b0.x, acc[im][in][3] + b0.y };
            *(float2*)(C + (size_t)r * N + cc) = v0;
            *(float2*)(C + (size_t)(r + 8) * N + cc) = v1;
        }
    }
}

// ---------------------------------------------------------------------------
// Flash attention (causal), fp32, one q-row per thread. Outputs bf16 hi/lo.
// ---------------------------------------------------------------------------
#define BQ_ 128
#define TK_ 32

__global__ __launch_bounds__(BQ_) void attn_kernel(
    const float* __restrict__ qkv,
    __nv_bfloat16* __restrict__ outh, __nv_bfloat16* __restrict__ outl)
{
    const int qt = blockIdx.x;
    const int h  = blockIdx.y;
    const int b  = blockIdx.z;
    const int tid = threadIdx.x;

    const int q_idx = qt * BQ_ + tid;
    const size_t qoff = (size_t)(b * L_ + q_idx) * E_ + h * HD_;

    float q[HD_], o[HD_];
    #pragma unroll
    for (int d = 0; d < HD_; d++) { q[d] = qkv[qoff + d]; o[d] = 0.f; }

    float m = -1e30f, l = 0.f;
    const float scale = 0.125f;

    __shared__ float Ks[TK_][HD_];
    __shared__ float Vs[TK_][HD_];

    const int kmax = qt * BQ_ + BQ_ - 1;

    for (int kt = 0; kt <= kmax; kt += TK_) {
        #pragma unroll
        for (int i = tid; i < TK_ * HD_; i += BQ_) {
            int j = i / HD_, d = i % HD_;
            size_t rk = (size_t)(b * L_ + kt + j) * E_;
            Ks[j][d] = qkv[rk + D_ + h * HD_ + d];
            Vs[j][d] = qkv[rk + 2 * D_ + h * HD_ + d];
        }
        __syncthreads();

        float s[TK_];
        float tmax = -1e30f;
        #pragma unroll 4
        for (int j = 0; j < TK_; j++) {
            if (kt + j <= q_idx) {
                float acc = 0.f;
                #pragma unroll
                for (int d = 0; d < HD_; d++) acc += q[d] * Ks[j][d];
                s[j] = acc * scale;
                tmax = fmaxf(tmax, s[j]);
            } else {
                s[j] = -1e30f;
            }
        }

        float mnew = fmaxf(m, tmax);
        float corr = __expf(m - mnew);
        l *= corr;
        #pragma unroll
        for (int d = 0; d < HD_; d++) o[d] *= corr;

        #pragma unroll 4
        for (int j = 0; j < TK_; j++) {
            float p = __expf(s[j] - mnew);
            l += p;
            #pragma unroll
            for (int d = 0; d < HD_; d++) o[d] += p * Vs[j][d];
        }
        m = mnew;
        __syncthreads();
    }

    const float inv = 1.0f / l;
    const size_t ooff = (size_t)(b * L_ + q_idx) * D_ + h * HD_;
    #pragma unroll
    for (int d = 0; d < HD_; d++) {
        float v = o[d] * inv;
        __nv_bfloat16 hh = __float2bfloat16(v);
        outh[ooff + d] = hh;
        outl[ooff + d] = __float2bfloat16(v - __bfloat162float(hh));
    }
}

// ---------------------------------------------------------------------------
extern "C" void kernel_launch(void* const* d_in, const int* in_sizes, int n_in,
                              void* d_out, int out_size)
{
    const float* x     = (const float*)d_in[0];  // [4,2048,1024]
    const float* w_in  = (const float*)d_in[1];  // [1024,3072]
    const float* b_in  = (const float*)d_in[2];  // [3072]
    const float* w_out = (const float*)d_in[3];  // [1024,1024]
    const float* b_out = (const float*)d_in[4];  // [1024]
    float* y = (float*)d_out;                    // [4,2048,1024]

    float *qkv = nullptr;
    __nv_bfloat16 *xh, *xl, *winh, *winl, *wouth, *woutl, *atth, *attl;
    cudaGetSymbolAddress((void**)&qkv,   g_qkv);
    cudaGetSymbolAddress((void**)&xh,    g_xh);
    cudaGetSymbolAddress((void**)&xl,    g_xl);
    cudaGetSymbolAddress((void**)&winh,  g_winT_h);
    cudaGetSymbolAddress((void**)&winl,  g_winT_l);
    cudaGetSymbolAddress((void**)&wouth, g_woutT_h);
    cudaGetSymbolAddress((void**)&woutl, g_woutT_l);
    cudaGetSymbolAddress((void**)&atth,  g_atth);
    cudaGetSymbolAddress((void**)&attl,  g_attl);

    static bool attr_set = false;
    if (!attr_set) {
        cudaFuncSetAttribute(gemm_mma_kernel, cudaFuncAttributeMaxDynamicSharedMemorySize, SMEMB);
        attr_set = true;
    }

    // prep: split x; transpose+split weights
    convert_split_kernel<<<4096, 256>>>(x, xh, xl, M_ * D_);
    {
        dim3 g(E_ / 32, D_ / 32); dim3 blk(32, 32);
        transpose_split_kernel<<<g, blk>>>(w_in, winh, winl, D_, E_);
    }
    {
        dim3 g(D_ / 32, D_ / 32); dim3 blk(32, 32);
        transpose_split_kernel<<<g, blk>>>(w_out, wouth, woutl, D_, D_);
    }

    // 1) QKV projection (tensor cores via mma.sync)
    {
        dim3 grid(E_ / 128, M_ / 128);
        gemm_mma_kernel<<<grid, 256, SMEMB>>>(xh, xl, winh, winl, b_in, qkv, M_, E_, D_);
    }

    // 2) Causal flash attention
    {
        dim3 grid(L_ / BQ_, H_, B_);
        attn_kernel<<<grid, BQ_>>>(qkv, atth, attl);
    }

    // 3) Output projection
    {
        dim3 grid(D_ / 128, M_ / 128);
        gemm_mma_kernel<<<grid, 256, SMEMB>>>(atth, attl, wouth, woutl, b_out, y, M_, D_, D_);
    }
}

// round 4
// speedup vs baseline: 3.5060x; 2.1315x over previous
#include <cuda_runtime.h>
#include <cuda_bf16.h>
#include <cstdint>

// ---------------------------------------------------------------------------
// Problem constants
// ---------------------------------------------------------------------------
#define B_   4
#define L_   2048
#define D_   1024
#define H_   16
#define HD_  64
#define E_   3072          // 3*D
#define M_   (B_ * L_)     // 8192 rows

// ---------------------------------------------------------------------------
// Scratch (device globals; no allocation allowed)
// ---------------------------------------------------------------------------
__device__ __nv_bfloat16  g_qkvh[(size_t)M_ * E_];     // qkv hi/lo  [8192, 3072]
__device__ __nv_bfloat16  g_qkvl[(size_t)M_ * E_];
__device__ __nv_bfloat16  g_vth[(size_t)(B_*H_*HD_) * L_];  // V^T hi/lo [4096, 2048]
__device__ __nv_bfloat16  g_vtl[(size_t)(B_*H_*HD_) * L_];
__device__ __nv_bfloat16  g_xh[(size_t)M_ * D_];       // x hi/lo
__device__ __nv_bfloat16  g_xl[(size_t)M_ * D_];
__device__ __nv_bfloat16  g_winT_h[(size_t)E_ * D_];   // w_in^T [3072,1024]
__device__ __nv_bfloat16  g_winT_l[(size_t)E_ * D_];
__device__ __nv_bfloat16  g_woutT_h[(size_t)D_ * D_];  // w_out^T [1024,1024]
__device__ __nv_bfloat16  g_woutT_l[(size_t)D_ * D_];
__device__ __nv_bfloat16  g_atth[(size_t)M_ * D_];     // attention out hi/lo
__device__ __nv_bfloat16  g_attl[(size_t)M_ * D_];

// ---------------------------------------------------------------------------
// Helpers
// ---------------------------------------------------------------------------
__device__ __forceinline__ uint32_t smem_u32(const void* p) {
    uint32_t a;
    asm("{ .reg .u64 t; cvta.to.shared.u64 t, %1; cvt.u32.u64 %0, t; }" : "=r"(a) : "l"(p));
    return a;
}

#define CP_ASYNC16(saddr, gptr) \
    asm volatile("cp.async.cg.shared.global [%0], [%1], 16;" :: "r"(saddr), "l"(gptr))
#define CP_COMMIT() asm volatile("cp.async.commit_group;" ::: "memory")
#define CP_WAIT(n)  asm volatile("cp.async.wait_group %0;" :: "n"(n) : "memory")

__device__ __forceinline__ void mma_bf16(float& c0, float& c1, float& c2, float& c3,
                                         uint32_t a0, uint32_t a1, uint32_t a2, uint32_t a3,
                                         uint32_t b0, uint32_t b1) {
    asm volatile(
        "mma.sync.aligned.m16n8k16.row.col.f32.bf16.bf16.f32 "
        "{%0,%1,%2,%3}, {%4,%5,%6,%7}, {%8,%9}, {%0,%1,%2,%3};"
        : "+f"(c0), "+f"(c1), "+f"(c2), "+f"(c3)
        : "r"(a0), "r"(a1), "r"(a2), "r"(a3), "r"(b0), "r"(b1));
}

__device__ __forceinline__ uint32_t pack_bf16(float x, float y) {
    __nv_bfloat162 v = __float22bfloat162_rn(make_float2(x, y));
    return *reinterpret_cast<uint32_t*>(&v);
}

// ---------------------------------------------------------------------------
// Prep kernels
// ---------------------------------------------------------------------------
__global__ void convert_split_kernel(const float* __restrict__ src,
                                     __nv_bfloat16* __restrict__ hi,
                                     __nv_bfloat16* __restrict__ lo, int n)
{
    for (int i = blockIdx.x * blockDim.x + threadIdx.x; i < n; i += gridDim.x * blockDim.x) {
        float v = src[i];
        __nv_bfloat16 h = __float2bfloat16(v);
        hi[i] = h;
        lo[i] = __float2bfloat16(v - __bfloat162float(h));
    }
}

// src [K, N] row-major  ->  dst hi/lo [N, K] bf16
__global__ void transpose_split_kernel(const float* __restrict__ src,
                                       __nv_bfloat16* __restrict__ hi,
                                       __nv_bfloat16* __restrict__ lo, int K, int N)
{
    __shared__ float tile[32][33];
    int n0 = blockIdx.x * 32, k0 = blockIdx.y * 32;
    int tx = threadIdx.x, ty = threadIdx.y;
    tile[ty][tx] = src[(size_t)(k0 + ty) * N + n0 + tx];
    __syncthreads();
    float v = tile[tx][ty];
    __nv_bfloat16 h = __float2bfloat16(v);
    size_t o = (size_t)(n0 + ty) * K + k0 + tx;
    hi[o] = h;
    lo[o] = __float2bfloat16(v - __bfloat162float(h));
}

// Transpose V region of qkv into [(b,h,d), l] layout (hi & lo).
__global__ void transpose_v_kernel(const __nv_bfloat16* __restrict__ qh,
                                   const __nv_bfloat16* __restrict__ ql,
                                   __nv_bfloat16* __restrict__ vth,
                                   __nv_bfloat16* __restrict__ vtl)
{
    __shared__ __nv_bfloat16 th[32][33];
    __shared__ __nv_bfloat16 tl[32][33];
    int b  = blockIdx.z;
    int lt = blockIdx.x * 32;   // token base
    int ct = blockIdx.y * 32;   // channel base (0..1023)
    int tx = threadIdx.x, ty = threadIdx.y;
    size_t g = (size_t)(b * L_ + lt + ty) * E_ + 2 * D_ + ct + tx;
    th[ty][tx] = qh[g];
    tl[ty][tx] = ql[g];
    __syncthreads();
    size_t o = (size_t)(b * D_ + ct + ty) * L_ + lt + tx;
    vth[o] = th[tx][ty];
    vtl[o] = tl[tx][ty];
}

// ---------------------------------------------------------------------------
// mma.sync bf16 split GEMM:
//   C[M,N] = (Ah+Al)[M,K] @ (Bh+Bl)[N,K]^T + bias[N]
// SPLIT=false: fp32 C.  SPLIT=true: bf16 hi/lo outputs Ch, Cl.
// ---------------------------------------------------------------------------
#define BKG 32
#define ROWB 80
#define MATB (128 * ROWB)
#define STAGEB (4 * MATB)
#define SMEMB (2 * STAGEB)           // 81920

template <bool SPLIT>
__global__ __launch_bounds__(256, 2) void gemm_mma_kernel(
    const __nv_bfloat16* __restrict__ Ah, const __nv_bfloat16* __restrict__ Al,
    const __nv_bfloat16* __restrict__ Bh, const __nv_bfloat16* __restrict__ Bl,
    const float* __restrict__ bias, float* __restrict__ C,
    __nv_bfloat16* __restrict__ Ch, __nv_bfloat16* __restrict__ Cl,
    int M, int N, int K)
{
    extern __shared__ char sm[];
    const int tid  = threadIdx.x;
    const int lane = tid & 31;
    const int wid  = tid >> 5;
    const int wm   = wid & 1;
    const int wn   = wid >> 1;
    const int row0 = blockIdx.y * 128;
    const int col0 = blockIdx.x * 128;
    const uint32_t smem_base = smem_u32(sm);

    float acc[4][4][4];
    #pragma unroll
    for (int i = 0; i < 4; i++)
        #pragma unroll
        for (int j = 0; j < 4; j++)
            #pragma unroll
            for (int c = 0; c < 4; c++) acc[i][j][c] = 0.f;

    const int nk = K / BKG;

    auto load_stage = [&](int i) {
        const int k0 = i * BKG;
        const uint32_t sbase = smem_base + (i & 1) * STAGEB;
        #pragma unroll
        for (int t = 0; t < 2; t++) {
            int c = tid + t * 256;
            int r = c >> 2, c8 = c & 3;
            uint32_t so = r * ROWB + c8 * 16;
            size_t ga = (size_t)(row0 + r) * K + k0 + c8 * 8;
            size_t gb = (size_t)(col0 + r) * K + k0 + c8 * 8;
            CP_ASYNC16(sbase + 0 * MATB + so, Ah + ga);
            CP_ASYNC16(sbase + 1 * MATB + so, Al + ga);
            CP_ASYNC16(sbase + 2 * MATB + so, Bh + gb);
            CP_ASYNC16(sbase + 3 * MATB + so, Bl + gb);
        }
        CP_COMMIT();
    };

    load_stage(0);

    const int arow = (lane >> 2);
    const int acol = (lane & 3) * 2;

    for (int i = 0; i < nk; i++) {
        if (i + 1 < nk) load_stage(i + 1);
        if (i + 1 < nk) { CP_WAIT(1); } else { CP_WAIT(0); }
        __syncthreads();

        const char* st = sm + (i & 1) * STAGEB;
        const char* pA[2] = { st + 0 * MATB, st + 1 * MATB };
        const char* pB[2] = { st + 2 * MATB, st + 3 * MATB };

        #pragma unroll
        for (int kk = 0; kk < 2; kk++) {
            const int colb = (kk * 16 + acol) * 2;
            #pragma unroll
            for (int p = 0; p < 3; p++) {
                const char* Abase = pA[p == 2 ? 1 : 0];
                const char* Bbase = pB[p == 1 ? 1 : 0];
                uint32_t afr[4][4], bfr[4][2];
                #pragma unroll
                for (int im = 0; im < 4; im++) {
                    int r = wm * 64 + im * 16 + arow;
                    afr[im][0] = *(const uint32_t*)(Abase + r * ROWB + colb);
                    afr[im][1] = *(const uint32_t*)(Abase + (r + 8) * ROWB + colb);
                    afr[im][2] = *(const uint32_t*)(Abase + r * ROWB + colb + 16);
                    afr[im][3] = *(const uint32_t*)(Abase + (r + 8) * ROWB + colb + 16);
                }
                #pragma unroll
                for (int in = 0; in < 4; in++) {
                    int n = wn * 32 + in * 8 + arow;
                    bfr[in][0] = *(const uint32_t*)(Bbase + n * ROWB + colb);
                    bfr[in][1] = *(const uint32_t*)(Bbase + n * ROWB + colb + 16);
                }
                #pragma unroll
                for (int im = 0; im < 4; im++)
                    #pragma unroll
                    for (int in = 0; in < 4; in++)
                        mma_bf16(acc[im][in][0], acc[im][in][1], acc[im][in][2], acc[im][in][3],
                                 afr[im][0], afr[im][1], afr[im][2], afr[im][3],
                                 bfr[in][0], bfr[in][1]);
            }
        }
        __syncthreads();
    }

    #pragma unroll
    for (int im = 0; im < 4; im++) {
        int r = row0 + wm * 64 + im * 16 + arow;
        #pragma unroll
        for (int in = 0; in < 4; in++) {
            int cc = col0 + wn * 32 + in * 8 + acol;
            float2 b0 = *(const float2*)(bias + cc);
            float f0 = acc[im][in][0] + b0.x;
            float f1 = acc[im][in][1] + b0.y;
            float f2 = acc[im][in][2] + b0.x;
            float f3 = acc[im][in][3] + b0.y;
            if (!SPLIT) {
                *(float2*)(C + (size_t)r * N + cc) = make_float2(f0, f1);
                *(float2*)(C + (size_t)(r + 8) * N + cc) = make_float2(f2, f3);
            } else {
                uint32_t h0 = pack_bf16(f0, f1);
                uint32_t h1 = pack_bf16(f2, f3);
                float l0a = f0 - __bfloat162float(__float2bfloat16(f0));
                float l0b = f1 - __bfloat162float(__float2bfloat16(f1));
                float l1a = f2 - __bfloat162float(__float2bfloat16(f2));
                float l1b = f3 - __bfloat162float(__float2bfloat16(f3));
                *(uint32_t*)(Ch + (size_t)r * N + cc)       = h0;
                *(uint32_t*)(Ch + (size_t)(r + 8) * N + cc) = h1;
                *(uint32_t*)(Cl + (size_t)r * N + cc)       = pack_bf16(l0a, l0b);
                *(uint32_t*)(Cl + (size_t)(r + 8) * N + cc) = pack_bf16(l1a, l1b);
            }
        }
    }
}

// ---------------------------------------------------------------------------
// Tensor-core causal flash attention with bf16 hi/lo split.
// Block 256 thr (8 warps x 16 q-rows = 128 q-rows). kv tiles of 64, double buf.
// grid (L/128, H, B).
// ---------------------------------------------------------------------------
#define AT_ROWB 144                       // 64 bf16 = 128B + 16B pad
#define AT_QBYTES (128 * AT_ROWB)         // 18432 per Q matrix
#define AT_TBY (64 * AT_ROWB)             // 9216 per tile matrix
#define AT_STAGEB (4 * AT_TBY)            // Kh,Kl,Vh,Vl = 36864
#define AT_SMEM (2 * AT_QBYTES + 2 * AT_STAGEB)   // 110592

__global__ __launch_bounds__(256) void attn_mma_kernel(
    const __nv_bfloat16* __restrict__ qh_, const __nv_bfloat16* __restrict__ ql_,
    const __nv_bfloat16* __restrict__ vth_, const __nv_bfloat16* __restrict__ vtl_,
    __nv_bfloat16* __restrict__ outh, __nv_bfloat16* __restrict__ outl)
{
    extern __shared__ char sm[];
    const int tid  = threadIdx.x;
    const int lane = tid & 31;
    const int wid  = tid >> 5;
    const int qt = blockIdx.x, h = blockIdx.y, b = blockIdx.z;
    const int q0 = qt * 128;
    const uint32_t sb = smem_u32(sm);
    const int arow = lane >> 2;
    const int acol = lane & 3;
    const float SC2 = 0.18033688011f;   // 0.125 * log2(e)

    // ---- stage Q (hi+lo) ----
    #pragma unroll
    for (int t = 0; t < 4; t++) {
        int c = tid + t * 256;          // 0..1023
        int r = c >> 3, ch = c & 7;
        uint32_t so = r * AT_ROWB + ch * 16;
        size_t g = (size_t)(b * L_ + q0 + r) * E_ + h * HD_ + ch * 8;
        CP_ASYNC16(sb + so, qh_ + g);
        CP_ASYNC16(sb + AT_QBYTES + so, ql_ + g);
    }
    CP_COMMIT();

    auto load_kv = [&](int t2) {
        const int k0 = t2 * 64;
        const uint32_t sbase = sb + 2 * AT_QBYTES + (t2 & 1) * AT_STAGEB;
        #pragma unroll
        for (int u = 0; u < 2; u++) {
            int c = tid + u * 256;      // 0..511
            int r = c >> 3, ch = c & 7;
            uint32_t so = r * AT_ROWB + ch * 16;
            size_t gk = (size_t)(b * L_ + k0 + r) * E_ + D_ + h * HD_ + ch * 8;
            CP_ASYNC16(sbase + so, qh_ + gk);
            CP_ASYNC16(sbase + AT_TBY + so, ql_ + gk);
            size_t gv = (size_t)((b * H_ + h) * HD_ + r) * L_ + k0 + ch * 8;
            CP_ASYNC16(sbase + 2 * AT_TBY + so, vth_ + gv);
            CP_ASYNC16(sbase + 3 * AT_TBY + so, vtl_ + gv);
        }
        CP_COMMIT();
    };

    load_kv(0);
    CP_WAIT(0);
    __syncthreads();

    // ---- Q fragments (held in registers for whole kernel) ----
    uint32_t qhf[4][4], qlf[4][4];
    {
        const char* QH = sm;
        const char* QL = sm + AT_QBYTES;
        int r = wid * 16 + arow;
        #pragma unroll
        for (int kc = 0; kc < 4; kc++) {
            int colb = kc * 32 + acol * 4;
            qhf[kc][0] = *(const uint32_t*)(QH + r * AT_ROWB + colb);
            qhf[kc][1] = *(const uint32_t*)(QH + (r + 8) * AT_ROWB + colb);
            qhf[kc][2] = *(const uint32_t*)(QH + r * AT_ROWB + colb + 16);
            qhf[kc][3] = *(const uint32_t*)(QH + (r + 8) * AT_ROWB + colb + 16);
            qlf[kc][0] = *(const uint32_t*)(QL + r * AT_ROWB + colb);
            qlf[kc][1] = *(const uint32_t*)(QL + (r + 8) * AT_ROWB + colb);
            qlf[kc][2] = *(const uint32_t*)(QL + r * AT_ROWB + colb + 16);
            qlf[kc][3] = *(const uint32_t*)(QL + (r + 8) * AT_ROWB + colb + 16);
        }
    }

    float o[8][4];
    #pragma unroll
    for (int i = 0; i < 8; i++)
        #pragma unroll
        for (int j = 0; j < 4; j++) o[i][j] = 0.f;
    float m0 = -1e30f, m1 = -1e30f, l0 = 0.f, l1 = 0.f;

    const int rg0 = q0 + wid * 16 + arow;   // this thread's global q rows
    const int rg1 = rg0 + 8;
    const int nt = 2 * qt + 2;

    for (int t = 0; t < nt; t++) {
        if (t + 1 < nt) load_kv(t + 1);
        if (t + 1 < nt) { CP_WAIT(1); } else { CP_WAIT(0); }
        __syncthreads();

        const int k0 = t * 64;
        const char* st = sm + 2 * AT_QBYTES + (t & 1) * AT_STAGEB;
        const char* KH = st;
        const char* KL = st + AT_TBY;
        const char* VH = st + 2 * AT_TBY;
        const char* VL = st + 3 * AT_TBY;

        const bool active = (k0 <= q0 + wid * 16 + 15);
        if (active) {
            // ---- S = Q @ K^T (3-product split) ----
            float s[8][4];
            #pragma unroll
            for (int i = 0; i < 8; i++)
                #pragma unroll
                for (int j = 0; j < 4; j++) s[i][j] = 0.f;

            #pragma unroll
            for (int nc = 0; nc < 8; nc++) {
                int n = nc * 8 + arow;
                uint32_t bh[4][2], bl[4][2];
                #pragma unroll
                for (int kc = 0; kc < 4; kc++) {
                    int colb = kc * 32 + acol * 4;
                    bh[kc][0] = *(const uint32_t*)(KH + n * AT_ROWB + colb);
                    bh[kc][1] = *(const uint32_t*)(KH + n * AT_ROWB + colb + 16);
                    bl[kc][0] = *(const uint32_t*)(KL + n * AT_ROWB + colb);
                    bl[kc][1] = *(const uint32_t*)(KL + n * AT_ROWB + colb + 16);
                }
                #pragma unroll
                for (int kc = 0; kc < 4; kc++)
                    mma_bf16(s[nc][0], s[nc][1], s[nc][2], s[nc][3],
                             qhf[kc][0], qhf[kc][1], qhf[kc][2], qhf[kc][3],
                             bh[kc][0], bh[kc][1]);
                #pragma unroll
                for (int kc = 0; kc < 4; kc++)
                    mma_bf16(s[nc][0], s[nc][1], s[nc][2], s[nc][3],
                             qhf[kc][0], qhf[kc][1], qhf[kc][2], qhf[kc][3],
                             bl[kc][0], bl[kc][1]);
                #pragma unroll
                for (int kc = 0; kc < 4; kc++)
                    mma_bf16(s[nc][0], s[nc][1], s[nc][2], s[nc][3],
                             qlf[kc][0], qlf[kc][1], qlf[kc][2], qlf[kc][3],
                             bh[kc][0], bh[kc][1]);
            }

            // ---- causal mask ----
            if (k0 + 63 > q0 + wid * 16) {
                #pragma unroll
                for (int nc = 0; nc < 8; nc++) {
                    int kbase = k0 + nc * 8 + acol * 2;
                    #pragma unroll
                    for (int e = 0; e < 2; e++) {
                        if (kbase + e > rg0) s[nc][e]     = -1e30f;
                        if (kbase + e > rg1) s[nc][2 + e] = -1e30f;
                    }
                }
            }

            // ---- online softmax ----
            float tm0 = -1e30f, tm1 = -1e30f;
            #pragma unroll
            for (int nc = 0; nc < 8; nc++) {
                tm0 = fmaxf(tm0, fmaxf(s[nc][0], s[nc][1]));
                tm1 = fmaxf(tm1, fmaxf(s[nc][2], s[nc][3]));
            }
            tm0 = fmaxf(tm0, __shfl_xor_sync(0xffffffff, tm0, 1));
            tm0 = fmaxf(tm0, __shfl_xor_sync(0xffffffff, tm0, 2));
            tm1 = fmaxf(tm1, __shfl_xor_sync(0xffffffff, tm1, 1));
            tm1 = fmaxf(tm1, __shfl_xor_sync(0xffffffff, tm1, 2));

            float mn0 = fmaxf(m0, tm0);
            float mn1 = fmaxf(m1, tm1);
            float corr0 = exp2f((m0 - mn0) * SC2);
            float corr1 = exp2f((m1 - mn1) * SC2);

            float p[8][4];
            float rs0 = 0.f, rs1 = 0.f;
            #pragma unroll
            for (int nc = 0; nc < 8; nc++) {
                p[nc][0] = exp2f((s[nc][0] - mn0) * SC2);
                p[nc][1] = exp2f((s[nc][1] - mn0) * SC2);
                p[nc][2] = exp2f((s[nc][2] - mn1) * SC2);
                p[nc][3] = exp2f((s[nc][3] - mn1) * SC2);
                rs0 += p[nc][0] + p[nc][1];
                rs1 += p[nc][2] + p[nc][3];
            }
            rs0 += __shfl_xor_sync(0xffffffff, rs0, 1);
            rs0 += __shfl_xor_sync(0xffffffff, rs0, 2);
            rs1 += __shfl_xor_sync(0xffffffff, rs1, 1);
            rs1 += __shfl_xor_sync(0xffffffff, rs1, 2);

            l0 = l0 * corr0 + rs0;
            l1 = l1 * corr1 + rs1;
            m0 = mn0; m1 = mn1;
            #pragma unroll
            for (int nc = 0; nc < 8; nc++) {
                o[nc][0] *= corr0; o[nc][1] *= corr0;
                o[nc][2] *= corr1; o[nc][3] *= corr1;
            }

            // ---- pack P to bf16 hi/lo A-fragments ----
            uint32_t phf[4][4], plf[4][4];
            #pragma unroll
            for (int kc = 0; kc < 4; kc++) {
                const int n0c = 2 * kc, n1c = 2 * kc + 1;
                phf[kc][0] = pack_bf16(p[n0c][0], p[n0c][1]);
                phf[kc][1] = pack_bf16(p[n0c][2], p[n0c][3]);
                phf[kc][2] = pack_bf16(p[n1c][0], p[n1c][1]);
                phf[kc][3] = pack_bf16(p[n1c][2], p[n1c][3]);
                float e00 = p[n0c][0] - __bfloat162float(__float2bfloat16(p[n0c][0]));
                float e01 = p[n0c][1] - __bfloat162float(__float2bfloat16(p[n0c][1]));
                float e02 = p[n0c][2] - __bfloat162float(__float2bfloat16(p[n0c][2]));
                float e03 = p[n0c][3] - __bfloat162float(__float2bfloat16(p[n0c][3]));
                float e10 = p[n1c][0] - __bfloat162float(__float2bfloat16(p[n1c][0]));
                float e11 = p[n1c][1] - __bfloat162float(__float2bfloat16(p[n1c][1]));
                float e12 = p[n1c][2] - __bfloat162float(__float2bfloat16(p[n1c][2]));
                float e13 = p[n1c][3] - __bfloat162float(__float2bfloat16(p[n1c][3]));
                plf[kc][0] = pack_bf16(e00, e01);
                plf[kc][1] = pack_bf16(e02, e03);
                plf[kc][2] = pack_bf16(e10, e11);
                plf[kc][3] = pack_bf16(e12, e13);
            }

            // ---- O += P @ V (3-product split) ----
            #pragma unroll
            for (int nc = 0; nc < 8; nc++) {
                int n = nc * 8 + arow;
                uint32_t vh[4][2], vl[4][2];
                #pragma unroll
                for (int kc = 0; kc < 4; kc++) {
                    int colb = kc * 32 + acol * 4;
                    vh[kc][0] = *(const uint32_t*)(VH + n * AT_ROWB + colb);
                    vh[kc][1] = *(const uint32_t*)(VH + n * AT_ROWB + colb + 16);
                    vl[kc][0] = *(const uint32_t*)(VL + n * AT_ROWB + colb);
                    vl[kc][1] = *(const uint32_t*)(VL + n * AT_ROWB + colb + 16);
                }
                #pragma unroll
                for (int kc = 0; kc < 4; kc++)
                    mma_bf16(o[nc][0], o[nc][1], o[nc][2], o[nc][3],
                             phf[kc][0], phf[kc][1], phf[kc][2], phf[kc][3],
                             vh[kc][0], vh[kc][1]);
                #pragma unroll
                for (int kc = 0; kc < 4; kc++)
                    mma_bf16(o[nc][0], o[nc][1], o[nc][2], o[nc][3],
                             phf[kc][0], phf[kc][1], phf[kc][2], phf[kc][3],
                             vl[kc][0], vl[kc][1]);
                #pragma unroll
                for (int kc = 0; kc < 4; kc++)
                    mma_bf16(o[nc][0], o[nc][1], o[nc][2], o[nc][3],
                             plf[kc][0], plf[kc][1], plf[kc][2], plf[kc][3],
                             vh[kc][0], vh[kc][1]);
            }
        }
        __syncthreads();
    }

    // ---- epilogue: O /= l, write bf16 hi/lo ----
    const float inv0 = 1.f / l0;
    const float inv1 = 1.f / l1;
    const size_t tok0 = (size_t)(b * L_ + q0 + wid * 16 + arow);
    #pragma unroll
    for (int nc = 0; nc < 8; nc++) {
        int col = h * HD_ + nc * 8 + acol * 2;
        float f0 = o[nc][0] * inv0, f1 = o[nc][1] * inv0;
        float f2 = o[nc][2] * inv1, f3 = o[nc][3] * inv1;
        *(uint32_t*)(outh + tok0 * D_ + col)       = pack_bf16(f0, f1);
        *(uint32_t*)(outh + (tok0 + 8) * D_ + col) = pack_bf16(f2, f3);
        float e0 = f0 - __bfloat162float(__float2bfloat16(f0));
        float e1 = f1 - __bfloat162float(__float2bfloat16(f1));
        float e2 = f2 - __bfloat162float(__float2bfloat16(f2));
        float e3 = f3 - __bfloat162float(__float2bfloat16(f3));
        *(uint32_t*)(outl + tok0 * D_ + col)       = pack_bf16(e0, e1);
        *(uint32_t*)(outl + (tok0 + 8) * D_ + col) = pack_bf16(e2, e3);
    }
}

// ---------------------------------------------------------------------------
extern "C" void kernel_launch(void* const* d_in, const int* in_sizes, int n_in,
                              void* d_out, int out_size)
{
    const float* x     = (const float*)d_in[0];
    const float* w_in  = (const float*)d_in[1];
    const float* b_in  = (const float*)d_in[2];
    const float* w_out = (const float*)d_in[3];
    const float* b_out = (const float*)d_in[4];
    float* y = (float*)d_out;

    __nv_bfloat16 *qkvh, *qkvl, *vth, *vtl, *xh, *xl, *winh, *winl, *wouth, *woutl, *atth, *attl;
    cudaGetSymbolAddress((void**)&qkvh,  g_qkvh);
    cudaGetSymbolAddress((void**)&qkvl,  g_qkvl);
    cudaGetSymbolAddress((void**)&vth,   g_vth);
    cudaGetSymbolAddress((void**)&vtl,   g_vtl);
    cudaGetSymbolAddress((void**)&xh,    g_xh);
    cudaGetSymbolAddress((void**)&xl,    g_xl);
    cudaGetSymbolAddress((void**)&winh,  g_winT_h);
    cudaGetSymbolAddress((void**)&winl,  g_winT_l);
    cudaGetSymbolAddress((void**)&wouth, g_woutT_h);
    cudaGetSymbolAddress((void**)&woutl, g_woutT_l);
    cudaGetSymbolAddress((void**)&atth,  g_atth);
    cudaGetSymbolAddress((void**)&attl,  g_attl);

    static bool attr_set = false;
    if (!attr_set) {
        cudaFuncSetAttribute(gemm_mma_kernel<true>,  cudaFuncAttributeMaxDynamicSharedMemorySize, SMEMB);
        cudaFuncSetAttribute(gemm_mma_kernel<false>, cudaFuncAttributeMaxDynamicSharedMemorySize, SMEMB);
        cudaFuncSetAttribute(attn_mma_kernel, cudaFuncAttributeMaxDynamicSharedMemorySize, AT_SMEM);
        attr_set = true;
    }

    // prep
    convert_split_kernel<<<4096, 256>>>(x, xh, xl, M_ * D_);
    {
        dim3 g(E_ / 32, D_ / 32); dim3 blk(32, 32);
        transpose_split_kernel<<<g, blk>>>(w_in, winh, winl, D_, E_);
    }
    {
        dim3 g(D_ / 32, D_ / 32); dim3 blk(32, 32);
        transpose_split_kernel<<<g, blk>>>(w_out, wouth, woutl, D_, D_);
    }

    // 1) QKV projection -> bf16 hi/lo
    {
        dim3 grid(E_ / 128, M_ / 128);
        gemm_mma_kernel<true><<<grid, 256, SMEMB>>>(
            xh, xl, winh, winl, b_in, nullptr, qkvh, qkvl, M_, E_, D_);
    }

    // 1b) transpose V region
    {
        dim3 g(L_ / 32, D_ / 32, B_); dim3 blk(32, 32);
        transpose_v_kernel<<<g, blk>>>(qkvh, qkvl, vth, vtl);
    }

    // 2) tensor-core causal flash attention
    {
        dim3 grid(L_ / 128, H_, B_);
        attn_mma_kernel<<<grid, 256, AT_SMEM>>>(qkvh, qkvl, vth, vtl, atth, attl);
    }

    // 3) output projection -> fp32 y
    {
        dim3 grid(D_ / 128, M_ / 128);
        gemm_mma_kernel<false><<<grid, 256, SMEMB>>>(
            atth, attl, wouth, woutl, b_out, y, nullptr, nullptr, M_, D_, D_);
    }
}

// round 5
// speedup vs baseline: 3.9252x; 1.1196x over previous
#include <cuda_runtime.h>
#include <cuda_bf16.h>
#include <cstdint>

// ---------------------------------------------------------------------------
// Problem constants
// ---------------------------------------------------------------------------
#define B_   4
#define L_   2048
#define D_   1024
#define H_   16
#define HD_  64
#define E_   3072          // 3*D
#define M_   (B_ * L_)     // 8192 rows

// ---------------------------------------------------------------------------
// Scratch (device globals; no allocation allowed)
// ---------------------------------------------------------------------------
__device__ __nv_bfloat16  g_qkvh[(size_t)M_ * E_];     // qkv hi/lo  [8192, 3072]
__device__ __nv_bfloat16  g_qkvl[(size_t)M_ * E_];
__device__ __nv_bfloat16  g_vth[(size_t)(B_*H_*HD_) * L_];  // V^T hi/lo [4096, 2048]
__device__ __nv_bfloat16  g_vtl[(size_t)(B_*H_*HD_) * L_];
__device__ __nv_bfloat16  g_xh[(size_t)M_ * D_];       // x hi/lo
__device__ __nv_bfloat16  g_xl[(size_t)M_ * D_];
__device__ __nv_bfloat16  g_winT_h[(size_t)E_ * D_];   // w_in^T [3072,1024]
__device__ __nv_bfloat16  g_winT_l[(size_t)E_ * D_];
__device__ __nv_bfloat16  g_woutT_h[(size_t)D_ * D_];  // w_out^T [1024,1024]
__device__ __nv_bfloat16  g_woutT_l[(size_t)D_ * D_];
__device__ __nv_bfloat16  g_atth[(size_t)M_ * D_];     // attention out hi/lo
__device__ __nv_bfloat16  g_attl[(size_t)M_ * D_];

// ---------------------------------------------------------------------------
// Helpers
// ---------------------------------------------------------------------------
__device__ __forceinline__ uint32_t smem_u32(const void* p) {
    uint32_t a;
    asm("{ .reg .u64 t; cvta.to.shared.u64 t, %1; cvt.u32.u64 %0, t; }" : "=r"(a) : "l"(p));
    return a;
}

#define CP_ASYNC16(saddr, gptr) \
    asm volatile("cp.async.cg.shared.global [%0], [%1], 16;" :: "r"(saddr), "l"(gptr))
#define CP_COMMIT() asm volatile("cp.async.commit_group;" ::: "memory")
#define CP_WAIT(n)  asm volatile("cp.async.wait_group %0;" :: "n"(n) : "memory")

__device__ __forceinline__ void mma_bf16(float& c0, float& c1, float& c2, float& c3,
                                         uint32_t a0, uint32_t a1, uint32_t a2, uint32_t a3,
                                         uint32_t b0, uint32_t b1) {
    asm volatile(
        "mma.sync.aligned.m16n8k16.row.col.f32.bf16.bf16.f32 "
        "{%0,%1,%2,%3}, {%4,%5,%6,%7}, {%8,%9}, {%0,%1,%2,%3};"
        : "+f"(c0), "+f"(c1), "+f"(c2), "+f"(c3)
        : "r"(a0), "r"(a1), "r"(a2), "r"(a3), "r"(b0), "r"(b1));
}

__device__ __forceinline__ void ldsm_x4(uint32_t& r0, uint32_t& r1, uint32_t& r2, uint32_t& r3,
                                        uint32_t addr) {
    asm volatile("ldmatrix.sync.aligned.m8n8.x4.shared.b16 {%0,%1,%2,%3}, [%4];"
                 : "=r"(r0), "=r"(r1), "=r"(r2), "=r"(r3) : "r"(addr));
}

__device__ __forceinline__ uint32_t pack_bf16(float x, float y) {
    __nv_bfloat162 v = __float22bfloat162_rn(make_float2(x, y));
    return *reinterpret_cast<uint32_t*>(&v);
}

// ---------------------------------------------------------------------------
// Prep kernels
// ---------------------------------------------------------------------------
__global__ void convert_split_kernel(const float* __restrict__ src,
                                     __nv_bfloat16* __restrict__ hi,
                                     __nv_bfloat16* __restrict__ lo, int n)
{
    for (int i = blockIdx.x * blockDim.x + threadIdx.x; i < n; i += gridDim.x * blockDim.x) {
        float v = src[i];
        __nv_bfloat16 h = __float2bfloat16(v);
        hi[i] = h;
        lo[i] = __float2bfloat16(v - __bfloat162float(h));
    }
}

// src [K, N] row-major  ->  dst hi/lo [N, K] bf16
__global__ void transpose_split_kernel(const float* __restrict__ src,
                                       __nv_bfloat16* __restrict__ hi,
                                       __nv_bfloat16* __restrict__ lo, int K, int N)
{
    __shared__ float tile[32][33];
    int n0 = blockIdx.x * 32, k0 = blockIdx.y * 32;
    int tx = threadIdx.x, ty = threadIdx.y;
    tile[ty][tx] = src[(size_t)(k0 + ty) * N + n0 + tx];
    __syncthreads();
    float v = tile[tx][ty];
    __nv_bfloat16 h = __float2bfloat16(v);
    size_t o = (size_t)(n0 + ty) * K + k0 + tx;
    hi[o] = h;
    lo[o] = __float2bfloat16(v - __bfloat162float(h));
}

// Transpose V region of qkv into [(b,h,d), l] layout (hi & lo).
__global__ void transpose_v_kernel(const __nv_bfloat16* __restrict__ qh,
                                   const __nv_bfloat16* __restrict__ ql,
                                   __nv_bfloat16* __restrict__ vth,
                                   __nv_bfloat16* __restrict__ vtl)
{
    __shared__ __nv_bfloat16 th[32][33];
    __shared__ __nv_bfloat16 tl[32][33];
    int b  = blockIdx.z;
    int lt = blockIdx.x * 32;
    int ct = blockIdx.y * 32;
    int tx = threadIdx.x, ty = threadIdx.y;
    size_t g = (size_t)(b * L_ + lt + ty) * E_ + 2 * D_ + ct + tx;
    th[ty][tx] = qh[g];
    tl[ty][tx] = ql[g];
    __syncthreads();
    size_t o = (size_t)(b * D_ + ct + ty) * L_ + lt + tx;
    vth[o] = th[tx][ty];
    vtl[o] = tl[tx][ty];
}

// ---------------------------------------------------------------------------
// mma.sync bf16 split GEMM (ldmatrix + non-redundant fragment loads):
//   C[M,N] = (Ah+Al)[M,K] @ (Bh+Bl)[N,K]^T + bias[N]
// ---------------------------------------------------------------------------
#define BKG 32
#define ROWB 80
#define MATB (128 * ROWB)
#define STAGEB (4 * MATB)
#define SMEMB (2 * STAGEB)           // 81920

template <bool SPLIT>
__global__ __launch_bounds__(256, 2) void gemm_mma_kernel(
    const __nv_bfloat16* __restrict__ Ah, const __nv_bfloat16* __restrict__ Al,
    const __nv_bfloat16* __restrict__ Bh, const __nv_bfloat16* __restrict__ Bl,
    const float* __restrict__ bias, float* __restrict__ C,
    __nv_bfloat16* __restrict__ Ch, __nv_bfloat16* __restrict__ Cl,
    int M, int N, int K)
{
    extern __shared__ char sm[];
    const int tid  = threadIdx.x;
    const int lane = tid & 31;
    const int wid  = tid >> 5;
    const int wm   = wid & 1;
    const int wn   = wid >> 1;
    const int row0 = blockIdx.y * 128;
    const int col0 = blockIdx.x * 128;
    const uint32_t smem_base = smem_u32(sm);

    float acc[4][4][4];
    #pragma unroll
    for (int i = 0; i < 4; i++)
        #pragma unroll
        for (int j = 0; j < 4; j++)
            #pragma unroll
            for (int c = 0; c < 4; c++) acc[i][j][c] = 0.f;

    const int nk = K / BKG;

    auto load_stage = [&](int i) {
        const int k0 = i * BKG;
        const uint32_t sbase = smem_base + (i & 1) * STAGEB;
        #pragma unroll
        for (int t = 0; t < 2; t++) {
            int c = tid + t * 256;
            int r = c >> 2, c8 = c & 3;
            uint32_t so = r * ROWB + c8 * 16;
            size_t ga = (size_t)(row0 + r) * K + k0 + c8 * 8;
            size_t gb = (size_t)(col0 + r) * K + k0 + c8 * 8;
            CP_ASYNC16(sbase + 0 * MATB + so, Ah + ga);
            CP_ASYNC16(sbase + 1 * MATB + so, Al + ga);
            CP_ASYNC16(sbase + 2 * MATB + so, Bh + gb);
            CP_ASYNC16(sbase + 3 * MATB + so, Bl + gb);
        }
        CP_COMMIT();
    };

    load_stage(0);

    // ldmatrix per-thread address components
    const int lr8 = lane & 7;
    const int aRow = wm * 64 + lr8 + ((lane & 8) ? 8 : 0);   // + im*16
    const int aCS  = (lane & 16) ? 16 : 0;
    const int bRow = wn * 32 + ((lane & 16) ? 8 : 0) + lr8;  // + inp*16
    const int bCS  = (lane & 8) ? 16 : 0;

    const int arow = (lane >> 2);
    const int acol = (lane & 3) * 2;

    for (int i = 0; i < nk; i++) {
        if (i + 1 < nk) load_stage(i + 1);
        if (i + 1 < nk) { CP_WAIT(1); } else { CP_WAIT(0); }
        __syncthreads();

        const uint32_t st = smem_base + (i & 1) * STAGEB;

        #pragma unroll
        for (int kk = 0; kk < 2; kk++) {
            const int kb = kk * 32;
            uint32_t ah[4][4], al[4][4], bh[2][4], bl[2][4];

            // load Ah + Bh, do p0 = Ah*Bh
            #pragma unroll
            for (int im = 0; im < 4; im++)
                ldsm_x4(ah[im][0], ah[im][1], ah[im][2], ah[im][3],
                        st + 0 * MATB + (uint32_t)(aRow + im * 16) * ROWB + kb + aCS);
            #pragma unroll
            for (int inp = 0; inp < 2; inp++)
                ldsm_x4(bh[inp][0], bh[inp][1], bh[inp][2], bh[inp][3],
                        st + 2 * MATB + (uint32_t)(bRow + inp * 16) * ROWB + kb + bCS);
            #pragma unroll
            for (int im = 0; im < 4; im++)
                #pragma unroll
                for (int in = 0; in < 4; in++)
                    mma_bf16(acc[im][in][0], acc[im][in][1], acc[im][in][2], acc[im][in][3],
                             ah[im][0], ah[im][1], ah[im][2], ah[im][3],
                             bh[in >> 1][(in & 1) * 2], bh[in >> 1][(in & 1) * 2 + 1]);

            // load Bl, p1 = Ah*Bl
            #pragma unroll
            for (int inp = 0; inp < 2; inp++)
                ldsm_x4(bl[inp][0], bl[inp][1], bl[inp][2], bl[inp][3],
                        st + 3 * MATB + (uint32_t)(bRow + inp * 16) * ROWB + kb + bCS);
            #pragma unroll
            for (int im = 0; im < 4; im++)
                #pragma unroll
                for (int in = 0; in < 4; in++)
                    mma_bf16(acc[im][in][0], acc[im][in][1], acc[im][in][2], acc[im][in][3],
                             ah[im][0], ah[im][1], ah[im][2], ah[im][3],
                             bl[in >> 1][(in & 1) * 2], bl[in >> 1][(in & 1) * 2 + 1]);

            // load Al, p2 = Al*Bh
            #pragma unroll
            for (int im = 0; im < 4; im++)
                ldsm_x4(al[im][0], al[im][1], al[im][2], al[im][3],
                        st + 1 * MATB + (uint32_t)(aRow + im * 16) * ROWB + kb + aCS);
            #pragma unroll
            for (int im = 0; im < 4; im++)
                #pragma unroll
                for (int in = 0; in < 4; in++)
                    mma_bf16(acc[im][in][0], acc[im][in][1], acc[im][in][2], acc[im][in][3],
                             al[im][0], al[im][1], al[im][2], al[im][3],
                             bh[in >> 1][(in & 1) * 2], bh[in >> 1][(in & 1) * 2 + 1]);
        }
        __syncthreads();
    }

    #pragma unroll
    for (int im = 0; im < 4; im++) {
        int r = row0 + wm * 64 + im * 16 + arow;
        #pragma unroll
        for (int in = 0; in < 4; in++) {
            int cc = col0 + wn * 32 + in * 8 + acol;
            float2 b0 = *(const float2*)(bias + cc);
            float f0 = acc[im][in][0] + b0.x;
            float f1 = acc[im][in][1] + b0.y;
            float f2 = acc[im][in][2] + b0.x;
            float f3 = acc[im][in][3] + b0.y;
            if (!SPLIT) {
                *(float2*)(C + (size_t)r * N + cc) = make_float2(f0, f1);
                *(float2*)(C + (size_t)(r + 8) * N + cc) = make_float2(f2, f3);
            } else {
                float l0a = f0 - __bfloat162float(__float2bfloat16(f0));
                float l0b = f1 - __bfloat162float(__float2bfloat16(f1));
                float l1a = f2 - __bfloat162float(__float2bfloat16(f2));
                float l1b = f3 - __bfloat162float(__float2bfloat16(f3));
                *(uint32_t*)(Ch + (size_t)r * N + cc)       = pack_bf16(f0, f1);
                *(uint32_t*)(Ch + (size_t)(r + 8) * N + cc) = pack_bf16(f2, f3);
                *(uint32_t*)(Cl + (size_t)r * N + cc)       = pack_bf16(l0a, l0b);
                *(uint32_t*)(Cl + (size_t)(r + 8) * N + cc) = pack_bf16(l1a, l1b);
            }
        }
    }
}

// ---------------------------------------------------------------------------
// Tensor-core causal flash attention with bf16 hi/lo split (ldmatrix loads).
// ---------------------------------------------------------------------------
#define AT_ROWB 144
#define AT_QBYTES (128 * AT_ROWB)
#define AT_TBY (64 * AT_ROWB)
#define AT_STAGEB (4 * AT_TBY)
#define AT_SMEM (2 * AT_QBYTES + 2 * AT_STAGEB)   // 110592

__global__ __launch_bounds__(256) void attn_mma_kernel(
    const __nv_bfloat16* __restrict__ qh_, const __nv_bfloat16* __restrict__ ql_,
    const __nv_bfloat16* __restrict__ vth_, const __nv_bfloat16* __restrict__ vtl_,
    __nv_bfloat16* __restrict__ outh, __nv_bfloat16* __restrict__ outl)
{
    extern __shared__ char sm[];
    const int tid  = threadIdx.x;
    const int lane = tid & 31;
    const int wid  = tid >> 5;
    const int qt = blockIdx.x, h = blockIdx.y, b = blockIdx.z;
    const int q0 = qt * 128;
    const uint32_t sb = smem_u32(sm);
    const int arow = lane >> 2;
    const int acol = lane & 3;
    const float SC2 = 0.18033688011f;   // 0.125 * log2(e)

    // ---- stage Q (hi+lo) ----
    #pragma unroll
    for (int t = 0; t < 4; t++) {
        int c = tid + t * 256;
        int r = c >> 3, ch = c & 7;
        uint32_t so = r * AT_ROWB + ch * 16;
        size_t g = (size_t)(b * L_ + q0 + r) * E_ + h * HD_ + ch * 8;
        CP_ASYNC16(sb + so, qh_ + g);
        CP_ASYNC16(sb + AT_QBYTES + so, ql_ + g);
    }
    CP_COMMIT();

    auto load_kv = [&](int t2) {
        const int k0 = t2 * 64;
        const uint32_t sbase = sb + 2 * AT_QBYTES + (t2 & 1) * AT_STAGEB;
        #pragma unroll
        for (int u = 0; u < 2; u++) {
            int c = tid + u * 256;
            int r = c >> 3, ch = c & 7;
            uint32_t so = r * AT_ROWB + ch * 16;
            size_t gk = (size_t)(b * L_ + k0 + r) * E_ + D_ + h * HD_ + ch * 8;
            CP_ASYNC16(sbase + so, qh_ + gk);
            CP_ASYNC16(sbase + AT_TBY + so, ql_ + gk);
            size_t gv = (size_t)((b * H_ + h) * HD_ + r) * L_ + k0 + ch * 8;
            CP_ASYNC16(sbase + 2 * AT_TBY + so, vth_ + gv);
            CP_ASYNC16(sbase + 3 * AT_TBY + so, vtl_ + gv);
        }
        CP_COMMIT();
    };

    load_kv(0);
    CP_WAIT(0);
    __syncthreads();

    // ---- Q fragments (in registers for whole kernel) ----
    uint32_t qhf[4][4], qlf[4][4];
    {
        const char* QH = sm;
        const char* QL = sm + AT_QBYTES;
        int r = wid * 16 + arow;
        #pragma unroll
        for (int kc = 0; kc < 4; kc++) {
            int colb = kc * 32 + acol * 4;
            qhf[kc][0] = *(const uint32_t*)(QH + r * AT_ROWB + colb);
            qhf[kc][1] = *(const uint32_t*)(QH + (r + 8) * AT_ROWB + colb);
            qhf[kc][2] = *(const uint32_t*)(QH + r * AT_ROWB + colb + 16);
            qhf[kc][3] = *(const uint32_t*)(QH + (r + 8) * AT_ROWB + colb + 16);
            qlf[kc][0] = *(const uint32_t*)(QL + r * AT_ROWB + colb);
            qlf[kc][1] = *(const uint32_t*)(QL + (r + 8) * AT_ROWB + colb);
            qlf[kc][2] = *(const uint32_t*)(QL + r * AT_ROWB + colb + 16);
            qlf[kc][3] = *(const uint32_t*)(QL + (r + 8) * AT_ROWB + colb + 16);
        }
    }

    float o[8][4];
    #pragma unroll
    for (int i = 0; i < 8; i++)
        #pragma unroll
        for (int j = 0; j < 4; j++) o[i][j] = 0.f;
    float m0 = -1e30f, m1 = -1e30f, l0 = 0.f, l1 = 0.f;

    const int rg0 = q0 + wid * 16 + arow;
    const int rg1 = rg0 + 8;
    const int nt = 2 * qt + 2;

    // ldmatrix address components for K/V B-fragments
    const int nR  = lane & 7;                  // + nc*8
    const int kcS = (lane & 16) ? 32 : 0;      // second kc of the pair
    const int cS  = (lane & 8) ? 16 : 0;

    for (int t = 0; t < nt; t++) {
        if (t + 1 < nt) load_kv(t + 1);
        if (t + 1 < nt) { CP_WAIT(1); } else { CP_WAIT(0); }
        __syncthreads();

        const int k0 = t * 64;
        const uint32_t st = sb + 2 * AT_QBYTES + (t & 1) * AT_STAGEB;
        const uint32_t KH = st;
        const uint32_t KL = st + AT_TBY;
        const uint32_t VH = st + 2 * AT_TBY;
        const uint32_t VL = st + 3 * AT_TBY;

        const bool active = (k0 <= q0 + wid * 16 + 15);
        if (active) {
            // ---- S = Q @ K^T (3-product split) ----
            float s[8][4];
            #pragma unroll
            for (int i = 0; i < 8; i++)
                #pragma unroll
                for (int j = 0; j < 4; j++) s[i][j] = 0.f;

            #pragma unroll
            for (int nc = 0; nc < 8; nc++) {
                uint32_t rowOff = (uint32_t)(nc * 8 + nR) * AT_ROWB + cS + kcS;
                uint32_t bh[4][2], bl[4][2];
                ldsm_x4(bh[0][0], bh[0][1], bh[1][0], bh[1][1], KH + rowOff);
                ldsm_x4(bh[2][0], bh[2][1], bh[3][0], bh[3][1], KH + rowOff + 64);
                ldsm_x4(bl[0][0], bl[0][1], bl[1][0], bl[1][1], KL + rowOff);
                ldsm_x4(bl[2][0], bl[2][1], bl[3][0], bl[3][1], KL + rowOff + 64);
                #pragma unroll
                for (int kc = 0; kc < 4; kc++)
                    mma_bf16(s[nc][0], s[nc][1], s[nc][2], s[nc][3],
                             qhf[kc][0], qhf[kc][1], qhf[kc][2], qhf[kc][3],
                             bh[kc][0], bh[kc][1]);
                #pragma unroll
                for (int kc = 0; kc < 4; kc++)
                    mma_bf16(s[nc][0], s[nc][1], s[nc][2], s[nc][3],
                             qhf[kc][0], qhf[kc][1], qhf[kc][2], qhf[kc][3],
                             bl[kc][0], bl[kc][1]);
                #pragma unroll
                for (int kc = 0; kc < 4; kc++)
                    mma_bf16(s[nc][0], s[nc][1], s[nc][2], s[nc][3],
                             qlf[kc][0], qlf[kc][1], qlf[kc][2], qlf[kc][3],
                             bh[kc][0], bh[kc][1]);
            }

            // ---- causal mask ----
            if (k0 + 63 > q0 + wid * 16) {
                #pragma unroll
                for (int nc = 0; nc < 8; nc++) {
                    int kbase = k0 + nc * 8 + acol * 2;
                    #pragma unroll
                    for (int e = 0; e < 2; e++) {
                        if (kbase + e > rg0) s[nc][e]     = -1e30f;
                        if (kbase + e > rg1) s[nc][2 + e] = -1e30f;
                    }
                }
            }

            // ---- online softmax ----
            float tm0 = -1e30f, tm1 = -1e30f;
            #pragma unroll
            for (int nc = 0; nc < 8; nc++) {
                tm0 = fmaxf(tm0, fmaxf(s[nc][0], s[nc][1]));
                tm1 = fmaxf(tm1, fmaxf(s[nc][2], s[nc][3]));
            }
            tm0 = fmaxf(tm0, __shfl_xor_sync(0xffffffff, tm0, 1));
            tm0 = fmaxf(tm0, __shfl_xor_sync(0xffffffff, tm0, 2));
            tm1 = fmaxf(tm1, __shfl_xor_sync(0xffffffff, tm1, 1));
            tm1 = fmaxf(tm1, __shfl_xor_sync(0xffffffff, tm1, 2));

            float mn0 = fmaxf(m0, tm0);
            float mn1 = fmaxf(m1, tm1);
            float corr0 = exp2f((m0 - mn0) * SC2);
            float corr1 = exp2f((m1 - mn1) * SC2);

            float p[8][4];
            float rs0 = 0.f, rs1 = 0.f;
            #pragma unroll
            for (int nc = 0; nc < 8; nc++) {
                p[nc][0] = exp2f((s[nc][0] - mn0) * SC2);
                p[nc][1] = exp2f((s[nc][1] - mn0) * SC2);
                p[nc][2] = exp2f((s[nc][2] - mn1) * SC2);
                p[nc][3] = exp2f((s[nc][3] - mn1) * SC2);
                rs0 += p[nc][0] + p[nc][1];
                rs1 += p[nc][2] + p[nc][3];
            }
            rs0 += __shfl_xor_sync(0xffffffff, rs0, 1);
            rs0 += __shfl_xor_sync(0xffffffff, rs0, 2);
            rs1 += __shfl_xor_sync(0xffffffff, rs1, 1);
            rs1 += __shfl_xor_sync(0xffffffff, rs1, 2);

            l0 = l0 * corr0 + rs0;
            l1 = l1 * corr1 + rs1;
            m0 = mn0; m1 = mn1;
            #pragma unroll
            for (int nc = 0; nc < 8; nc++) {
                o[nc][0] *= corr0; o[nc][1] *= corr0;
                o[nc][2] *= corr1; o[nc][3] *= corr1;
            }

            // ---- pack P to bf16 hi/lo A-fragments ----
            uint32_t phf[4][4], plf[4][4];
            #pragma unroll
            for (int kc = 0; kc < 4; kc++) {
                const int n0c = 2 * kc, n1c = 2 * kc + 1;
                phf[kc][0] = pack_bf16(p[n0c][0], p[n0c][1]);
                phf[kc][1] = pack_bf16(p[n0c][2], p[n0c][3]);
                phf[kc][2] = pack_bf16(p[n1c][0], p[n1c][1]);
                phf[kc][3] = pack_bf16(p[n1c][2], p[n1c][3]);
                float e00 = p[n0c][0] - __bfloat162float(__float2bfloat16(p[n0c][0]));
                float e01 = p[n0c][1] - __bfloat162float(__float2bfloat16(p[n0c][1]));
                float e02 = p[n0c][2] - __bfloat162float(__float2bfloat16(p[n0c][2]));
                float e03 = p[n0c][3] - __bfloat162float(__float2bfloat16(p[n0c][3]));
                float e10 = p[n1c][0] - __bfloat162float(__float2bfloat16(p[n1c][0]));
                float e11 = p[n1c][1] - __bfloat162float(__float2bfloat16(p[n1c][1]));
                float e12 = p[n1c][2] - __bfloat162float(__float2bfloat16(p[n1c][2]));
                float e13 = p[n1c][3] - __bfloat162float(__float2bfloat16(p[n1c][3]));
                plf[kc][0] = pack_bf16(e00, e01);
                plf[kc][1] = pack_bf16(e02, e03);
                plf[kc][2] = pack_bf16(e10, e11);
                plf[kc][3] = pack_bf16(e12, e13);
            }

            // ---- O += P @ V (3-product split) ----
            #pragma unroll
            for (int nc = 0; nc < 8; nc++) {
                uint32_t rowOff = (uint32_t)(nc * 8 + nR) * AT_ROWB + cS + kcS;
                uint32_t vh[4][2], vl[4][2];
                ldsm_x4(vh[0][0], vh[0][1], vh[1][0], vh[1][1], VH + rowOff);
                ldsm_x4(vh[2][0], vh[2][1], vh[3][0], vh[3][1], VH + rowOff + 64);
                ldsm_x4(vl[0][0], vl[0][1], vl[1][0], vl[1][1], VL + rowOff);
                ldsm_x4(vl[2][0], vl[2][1], vl[3][0], vl[3][1], VL + rowOff + 64);
                #pragma unroll
                for (int kc = 0; kc < 4; kc++)
                    mma_bf16(o[nc][0], o[nc][1], o[nc][2], o[nc][3],
                             phf[kc][0], phf[kc][1], phf[kc][2], phf[kc][3],
                             vh[kc][0], vh[kc][1]);
                #pragma unroll
                for (int kc = 0; kc < 4; kc++)
                    mma_bf16(o[nc][0], o[nc][1], o[nc][2], o[nc][3],
                             phf[kc][0], phf[kc][1], phf[kc][2], phf[kc][3],
                             vl[kc][0], vl[kc][1]);
                #pragma unroll
                for (int kc = 0; kc < 4; kc++)
                    mma_bf16(o[nc][0], o[nc][1], o[nc][2], o[nc][3],
                             plf[kc][0], plf[kc][1], plf[kc][2], plf[kc][3],
                             vh[kc][0], vh[kc][1]);
            }
        }
        __syncthreads();
    }

    // ---- epilogue: O /= l, write bf16 hi/lo ----
    const float inv0 = 1.f / l0;
    const float inv1 = 1.f / l1;
    const size_t tok0 = (size_t)(b * L_ + q0 + wid * 16 + arow);
    #pragma unroll
    for (int nc = 0; nc < 8; nc++) {
        int col = h * HD_ + nc * 8 + acol * 2;
        float f0 = o[nc][0] * inv0, f1 = o[nc][1] * inv0;
        float f2 = o[nc][2] * inv1, f3 = o[nc][3] * inv1;
        *(uint32_t*)(outh + tok0 * D_ + col)       = pack_bf16(f0, f1);
        *(uint32_t*)(outh + (tok0 + 8) * D_ + col) = pack_bf16(f2, f3);
        float e0 = f0 - __bfloat162float(__float2bfloat16(f0));
        float e1 = f1 - __bfloat162float(__float2bfloat16(f1));
        float e2 = f2 - __bfloat162float(__float2bfloat16(f2));
        float e3 = f3 - __bfloat162float(__float2bfloat16(f3));
        *(uint32_t*)(outl + tok0 * D_ + col)       = pack_bf16(e0, e1);
        *(uint32_t*)(outl + (tok0 + 8) * D_ + col) = pack_bf16(e2, e3);
    }
}

// ---------------------------------------------------------------------------
extern "C" void kernel_launch(void* const* d_in, const int* in_sizes, int n_in,
                              void* d_out, int out_size)
{
    const float* x     = (const float*)d_in[0];
    const float* w_in  = (const float*)d_in[1];
    const float* b_in  = (const float*)d_in[2];
    const float* w_out = (const float*)d_in[3];
    const float* b_out = (const float*)d_in[4];
    float* y = (float*)d_out;

    __nv_bfloat16 *qkvh, *qkvl, *vth, *vtl, *xh, *xl, *winh, *winl, *wouth, *woutl, *atth, *attl;
    cudaGetSymbolAddress((void**)&qkvh,  g_qkvh);
    cudaGetSymbolAddress((void**)&qkvl,  g_qkvl);
    cudaGetSymbolAddress((void**)&vth,   g_vth);
    cudaGetSymbolAddress((void**)&vtl,   g_vtl);
    cudaGetSymbolAddress((void**)&xh,    g_xh);
    cudaGetSymbolAddress((void**)&xl,    g_xl);
    cudaGetSymbolAddress((void**)&winh,  g_winT_h);
    cudaGetSymbolAddress((void**)&winl,  g_winT_l);
    cudaGetSymbolAddress((void**)&wouth, g_woutT_h);
    cudaGetSymbolAddress((void**)&woutl, g_woutT_l);
    cudaGetSymbolAddress((void**)&atth,  g_atth);
    cudaGetSymbolAddress((void**)&attl,  g_attl);

    static bool attr_set = false;
    if (!attr_set) {
        cudaFuncSetAttribute(gemm_mma_kernel<true>,  cudaFuncAttributeMaxDynamicSharedMemorySize, SMEMB);
        cudaFuncSetAttribute(gemm_mma_kernel<false>, cudaFuncAttributeMaxDynamicSharedMemorySize, SMEMB);
        cudaFuncSetAttribute(attn_mma_kernel, cudaFuncAttributeMaxDynamicSharedMemorySize, AT_SMEM);
        attr_set = true;
    }

    // prep
    convert_split_kernel<<<4096, 256>>>(x, xh, xl, M_ * D_);
    {
        dim3 g(E_ / 32, D_ / 32); dim3 blk(32, 32);
        transpose_split_kernel<<<g, blk>>>(w_in, winh, winl, D_, E_);
    }
    {
        dim3 g(D_ / 32, D_ / 32); dim3 blk(32, 32);
        transpose_split_kernel<<<g, blk>>>(w_out, wouth, woutl, D_, D_);
    }

    // 1) QKV projection -> bf16 hi/lo
    {
        dim3 grid(E_ / 128, M_ / 128);
        gemm_mma_kernel<true><<<grid, 256, SMEMB>>>(
            xh, xl, winh, winl, b_in, nullptr, qkvh, qkvl, M_, E_, D_);
    }

    // 1b) transpose V region
    {
        dim3 g(L_ / 32, D_ / 32, B_); dim3 blk(32, 32);
        transpose_v_kernel<<<g, blk>>>(qkvh, qkvl, vth, vtl);
    }

    // 2) tensor-core causal flash attention
    {
        dim3 grid(L_ / 128, H_, B_);
        attn_mma_kernel<<<grid, 256, AT_SMEM>>>(qkvh, qkvl, vth, vtl, atth, attl);
    }

    // 3) output projection -> fp32 y
    {
        dim3 grid(D_ / 128, M_ / 128);
        gemm_mma_kernel<false><<<grid, 256, SMEMB>>>(
            atth, attl, wouth, woutl, b_out, y, nullptr, nullptr, M_, D_, D_);
    }
}

// round 6
// speedup vs baseline: 8.8268x; 2.2488x over previous
#include <cuda_runtime.h>
#include <cuda_fp16.h>
#include <cstdint>

// ---------------------------------------------------------------------------
// Problem constants
// ---------------------------------------------------------------------------
#define B_   4
#define L_   2048
#define D_   1024
#define H_   16
#define HD_  64
#define E_   3072          // 3*D
#define M_   (B_ * L_)     // 8192 rows

// ---------------------------------------------------------------------------
// Scratch (device globals; no allocation allowed)
// ---------------------------------------------------------------------------
__device__ __half g_qkv[(size_t)M_ * E_];          // qkv fp16 [8192, 3072]
__device__ __half g_vt[(size_t)(B_*H_*HD_) * L_];  // V^T fp16 [4096, 2048]
__device__ __half g_x16[(size_t)M_ * D_];          // x fp16
__device__ __half g_winT[(size_t)E_ * D_];         // w_in^T  [3072,1024]
__device__ __half g_woutT[(size_t)D_ * D_];        // w_out^T [1024,1024]
__device__ __half g_att[(size_t)M_ * D_];          // attention out fp16

// ---------------------------------------------------------------------------
// Helpers
// ---------------------------------------------------------------------------
__device__ __forceinline__ uint32_t smem_u32(const void* p) {
    uint32_t a;
    asm("{ .reg .u64 t; cvta.to.shared.u64 t, %1; cvt.u32.u64 %0, t; }" : "=r"(a) : "l"(p));
    return a;
}

#define CP_ASYNC16(saddr, gptr) \
    asm volatile("cp.async.cg.shared.global [%0], [%1], 16;" :: "r"(saddr), "l"(gptr))
#define CP_COMMIT() asm volatile("cp.async.commit_group;" ::: "memory")
#define CP_WAIT(n)  asm volatile("cp.async.wait_group %0;" :: "n"(n) : "memory")

__device__ __forceinline__ void mma_f16(float& c0, float& c1, float& c2, float& c3,
                                        uint32_t a0, uint32_t a1, uint32_t a2, uint32_t a3,
                                        uint32_t b0, uint32_t b1) {
    asm volatile(
        "mma.sync.aligned.m16n8k16.row.col.f32.f16.f16.f32 "
        "{%0,%1,%2,%3}, {%4,%5,%6,%7}, {%8,%9}, {%0,%1,%2,%3};"
        : "+f"(c0), "+f"(c1), "+f"(c2), "+f"(c3)
        : "r"(a0), "r"(a1), "r"(a2), "r"(a3), "r"(b0), "r"(b1));
}

__device__ __forceinline__ void ldsm_x4(uint32_t& r0, uint32_t& r1, uint32_t& r2, uint32_t& r3,
                                        uint32_t addr) {
    asm volatile("ldmatrix.sync.aligned.m8n8.x4.shared.b16 {%0,%1,%2,%3}, [%4];"
                 : "=r"(r0), "=r"(r1), "=r"(r2), "=r"(r3) : "r"(addr));
}

__device__ __forceinline__ uint32_t pack_h2(float x, float y) {
    __half2 v = __floats2half2_rn(x, y);
    return *reinterpret_cast<uint32_t*>(&v);
}

// ---------------------------------------------------------------------------
// Prep kernels
// ---------------------------------------------------------------------------
__global__ void convert_f16_kernel(const float* __restrict__ src,
                                   __half* __restrict__ dst, int n)
{
    for (int i = blockIdx.x * blockDim.x + threadIdx.x; i < n; i += gridDim.x * blockDim.x)
        dst[i] = __float2half_rn(src[i]);
}

// src [K, N] row-major -> dst [N, K] fp16
__global__ void transpose_f16_kernel(const float* __restrict__ src,
                                     __half* __restrict__ dst, int K, int N)
{
    __shared__ float tile[32][33];
    int n0 = blockIdx.x * 32, k0 = blockIdx.y * 32;
    int tx = threadIdx.x, ty = threadIdx.y;
    tile[ty][tx] = src[(size_t)(k0 + ty) * N + n0 + tx];
    __syncthreads();
    dst[(size_t)(n0 + ty) * K + k0 + tx] = __float2half_rn(tile[tx][ty]);
}

// Transpose V region of qkv into [(b,h,d), l] layout.
__global__ void transpose_v_kernel(const __half* __restrict__ qkv,
                                   __half* __restrict__ vt)
{
    __shared__ __half t[32][33];
    int b  = blockIdx.z;
    int lt = blockIdx.x * 32;
    int ct = blockIdx.y * 32;
    int tx = threadIdx.x, ty = threadIdx.y;
    t[ty][tx] = qkv[(size_t)(b * L_ + lt + ty) * E_ + 2 * D_ + ct + tx];
    __syncthreads();
    vt[(size_t)(b * D_ + ct + ty) * L_ + lt + tx] = t[tx][ty];
}

// ---------------------------------------------------------------------------
// fp16 single-product GEMM: C[M,N] = A[M,K] @ B[N,K]^T + bias[N]
// 128x128x32 tiles, 8 warps (2x4, warp 64x32), 3-stage cp.async pipeline.
// OUT_HALF: write fp16 Ch, else fp32 C.
// ---------------------------------------------------------------------------
#define BKG 32
#define ROWB 80                       // 32 fp16 = 64B + 16B pad
#define MATB (128 * ROWB)             // 10240
#define STAGEB (2 * MATB)             // A + B = 20480
#define NSTAGE 3
#define SMEMB (NSTAGE * STAGEB)       // 61440

template <bool OUT_HALF>
__global__ __launch_bounds__(256, 2) void gemm_mma_kernel(
    const __half* __restrict__ A, const __half* __restrict__ Bm,
    const float* __restrict__ bias, float* __restrict__ C,
    __half* __restrict__ Ch,
    int M, int N, int K)
{
    extern __shared__ char sm[];
    const int tid  = threadIdx.x;
    const int lane = tid & 31;
    const int wid  = tid >> 5;
    const int wm   = wid & 1;
    const int wn   = wid >> 1;
    const int row0 = blockIdx.y * 128;
    const int col0 = blockIdx.x * 128;
    const uint32_t smem_base = smem_u32(sm);

    float acc[4][4][4];
    #pragma unroll
    for (int i = 0; i < 4; i++)
        #pragma unroll
        for (int j = 0; j < 4; j++)
            #pragma unroll
            for (int c = 0; c < 4; c++) acc[i][j][c] = 0.f;

    const int nk = K / BKG;

    auto load_stage = [&](int i) {
        const int k0 = i * BKG;
        const uint32_t sbase = smem_base + (i % NSTAGE) * STAGEB;
        #pragma unroll
        for (int t = 0; t < 2; t++) {
            int c = tid + t * 256;
            int r = c >> 2, c8 = c & 3;
            uint32_t so = r * ROWB + c8 * 16;
            size_t ga = (size_t)(row0 + r) * K + k0 + c8 * 8;
            size_t gb = (size_t)(col0 + r) * K + k0 + c8 * 8;
            CP_ASYNC16(sbase + 0 * MATB + so, A + ga);
            CP_ASYNC16(sbase + 1 * MATB + so, Bm + gb);
        }
        CP_COMMIT();
    };

    load_stage(0);
    load_stage(1);

    const int lr8 = lane & 7;
    const int aRow = wm * 64 + lr8 + ((lane & 8) ? 8 : 0);
    const int aCS  = (lane & 16) ? 16 : 0;
    const int bRow = wn * 32 + ((lane & 16) ? 8 : 0) + lr8;
    const int bCS  = (lane & 8) ? 16 : 0;

    const int arow = (lane >> 2);
    const int acol = (lane & 3) * 2;

    for (int i = 0; i < nk; i++) {
        if (i + 2 < nk) { load_stage(i + 2); CP_WAIT(2); }
        else if (i + 1 < nk) { CP_WAIT(1); }
        else { CP_WAIT(0); }
        __syncthreads();

        const uint32_t st = smem_base + (i % NSTAGE) * STAGEB;

        #pragma unroll
        for (int kk = 0; kk < 2; kk++) {
            const int kb = kk * 32;
            uint32_t ah[4][4], bh[2][4];
            #pragma unroll
            for (int im = 0; im < 4; im++)
                ldsm_x4(ah[im][0], ah[im][1], ah[im][2], ah[im][3],
                        st + 0 * MATB + (uint32_t)(aRow + im * 16) * ROWB + kb + aCS);
            #pragma unroll
            for (int inp = 0; inp < 2; inp++)
                ldsm_x4(bh[inp][0], bh[inp][1], bh[inp][2], bh[inp][3],
                        st + 1 * MATB + (uint32_t)(bRow + inp * 16) * ROWB + kb + bCS);
            #pragma unroll
            for (int im = 0; im < 4; im++)
                #pragma unroll
                for (int in = 0; in < 4; in++)
                    mma_f16(acc[im][in][0], acc[im][in][1], acc[im][in][2], acc[im][in][3],
                            ah[im][0], ah[im][1], ah[im][2], ah[im][3],
                            bh[in >> 1][(in & 1) * 2], bh[in >> 1][(in & 1) * 2 + 1]);
        }
        __syncthreads();
    }

    #pragma unroll
    for (int im = 0; im < 4; im++) {
        int r = row0 + wm * 64 + im * 16 + arow;
        #pragma unroll
        for (int in = 0; in < 4; in++) {
            int cc = col0 + wn * 32 + in * 8 + acol;
            float2 b0 = *(const float2*)(bias + cc);
            float f0 = acc[im][in][0] + b0.x;
            float f1 = acc[im][in][1] + b0.y;
            float f2 = acc[im][in][2] + b0.x;
            float f3 = acc[im][in][3] + b0.y;
            if (OUT_HALF) {
                *(uint32_t*)(Ch + (size_t)r * N + cc)       = pack_h2(f0, f1);
                *(uint32_t*)(Ch + (size_t)(r + 8) * N + cc) = pack_h2(f2, f3);
            } else {
                *(float2*)(C + (size_t)r * N + cc)       = make_float2(f0, f1);
                *(float2*)(C + (size_t)(r + 8) * N + cc) = make_float2(f2, f3);
            }
        }
    }
}

// ---------------------------------------------------------------------------
// fp16 tensor-core causal flash attention.
// Block 256 thr (8 warps x 16 q-rows = 128 q-rows). kv tiles of 64, double buf.
// ---------------------------------------------------------------------------
#define AT_ROWB 144                       // 64 fp16 = 128B + 16B pad
#define AT_QBYTES (128 * AT_ROWB)         // 18432
#define AT_TBY (64 * AT_ROWB)             // 9216
#define AT_STAGEB (2 * AT_TBY)            // K + V = 18432
#define AT_SMEM (AT_QBYTES + 2 * AT_STAGEB)   // 55296

__global__ __launch_bounds__(256, 2) void attn_mma_kernel(
    const __half* __restrict__ qkv, const __half* __restrict__ vt,
    __half* __restrict__ out)
{
    extern __shared__ char sm[];
    const int tid  = threadIdx.x;
    const int lane = tid & 31;
    const int wid  = tid >> 5;
    const int qt = blockIdx.x, h = blockIdx.y, b = blockIdx.z;
    const int q0 = qt * 128;
    const uint32_t sb = smem_u32(sm);
    const int arow = lane >> 2;
    const int acol = lane & 3;
    const float SC2 = 0.18033688011f;   // 0.125 * log2(e)

    // ---- stage Q ----
    #pragma unroll
    for (int t = 0; t < 4; t++) {
        int c = tid + t * 256;
        int r = c >> 3, ch = c & 7;
        size_t g = (size_t)(b * L_ + q0 + r) * E_ + h * HD_ + ch * 8;
        CP_ASYNC16(sb + r * AT_ROWB + ch * 16, qkv + g);
    }
    CP_COMMIT();

    auto load_kv = [&](int t2) {
        const int k0 = t2 * 64;
        const uint32_t sbase = sb + AT_QBYTES + (t2 & 1) * AT_STAGEB;
        #pragma unroll
        for (int u = 0; u < 2; u++) {
            int c = tid + u * 256;
            int r = c >> 3, ch = c & 7;
            uint32_t so = r * AT_ROWB + ch * 16;
            size_t gk = (size_t)(b * L_ + k0 + r) * E_ + D_ + h * HD_ + ch * 8;
            CP_ASYNC16(sbase + so, qkv + gk);
            size_t gv = (size_t)((b * H_ + h) * HD_ + r) * L_ + k0 + ch * 8;
            CP_ASYNC16(sbase + AT_TBY + so, vt + gv);
        }
        CP_COMMIT();
    };

    load_kv(0);
    CP_WAIT(0);
    __syncthreads();

    // ---- Q fragments (registers for whole kernel) ----
    uint32_t qf[4][4];
    {
        const char* QH = sm;
        int r = wid * 16 + arow;
        #pragma unroll
        for (int kc = 0; kc < 4; kc++) {
            int colb = kc * 32 + acol * 4;
            qf[kc][0] = *(const uint32_t*)(QH + r * AT_ROWB + colb);
            qf[kc][1] = *(const uint32_t*)(QH + (r + 8) * AT_ROWB + colb);
            qf[kc][2] = *(const uint32_t*)(QH + r * AT_ROWB + colb + 16);
            qf[kc][3] = *(const uint32_t*)(QH + (r + 8) * AT_ROWB + colb + 16);
        }
    }

    float o[8][4];
    #pragma unroll
    for (int i = 0; i < 8; i++)
        #pragma unroll
        for (int j = 0; j < 4; j++) o[i][j] = 0.f;
    float m0 = -1e30f, m1 = -1e30f, l0 = 0.f, l1 = 0.f;

    const int rg0 = q0 + wid * 16 + arow;
    const int rg1 = rg0 + 8;
    const int nt = 2 * qt + 2;

    const int nR  = lane & 7;
    const int kcS = (lane & 16) ? 32 : 0;
    const int cS  = (lane & 8) ? 16 : 0;

    for (int t = 0; t < nt; t++) {
        if (t + 1 < nt) load_kv(t + 1);
        if (t + 1 < nt) { CP_WAIT(1); } else { CP_WAIT(0); }
        __syncthreads();

        const int k0 = t * 64;
        const uint32_t st = sb + AT_QBYTES + (t & 1) * AT_STAGEB;
        const uint32_t KH = st;
        const uint32_t VH = st + AT_TBY;

        const bool active = (k0 <= q0 + wid * 16 + 15);
        if (active) {
            // ---- S = Q @ K^T ----
            float s[8][4];
            #pragma unroll
            for (int i = 0; i < 8; i++)
                #pragma unroll
                for (int j = 0; j < 4; j++) s[i][j] = 0.f;

            #pragma unroll
            for (int nc = 0; nc < 8; nc++) {
                uint32_t rowOff = (uint32_t)(nc * 8 + nR) * AT_ROWB + cS + kcS;
                uint32_t bh[4][2];
                ldsm_x4(bh[0][0], bh[0][1], bh[1][0], bh[1][1], KH + rowOff);
                ldsm_x4(bh[2][0], bh[2][1], bh[3][0], bh[3][1], KH + rowOff + 64);
                #pragma unroll
                for (int kc = 0; kc < 4; kc++)
                    mma_f16(s[nc][0], s[nc][1], s[nc][2], s[nc][3],
                            qf[kc][0], qf[kc][1], qf[kc][2], qf[kc][3],
                            bh[kc][0], bh[kc][1]);
            }

            // ---- causal mask ----
            if (k0 + 63 > q0 + wid * 16) {
                #pragma unroll
                for (int nc = 0; nc < 8; nc++) {
                    int kbase = k0 + nc * 8 + acol * 2;
                    #pragma unroll
                    for (int e = 0; e < 2; e++) {
                        if (kbase + e > rg0) s[nc][e]     = -1e30f;
                        if (kbase + e > rg1) s[nc][2 + e] = -1e30f;
                    }
                }
            }

            // ---- online softmax ----
            float tm0 = -1e30f, tm1 = -1e30f;
            #pragma unroll
            for (int nc = 0; nc < 8; nc++) {
                tm0 = fmaxf(tm0, fmaxf(s[nc][0], s[nc][1]));
                tm1 = fmaxf(tm1, fmaxf(s[nc][2], s[nc][3]));
            }
            tm0 = fmaxf(tm0, __shfl_xor_sync(0xffffffff, tm0, 1));
            tm0 = fmaxf(tm0, __shfl_xor_sync(0xffffffff, tm0, 2));
            tm1 = fmaxf(tm1, __shfl_xor_sync(0xffffffff, tm1, 1));
            tm1 = fmaxf(tm1, __shfl_xor_sync(0xffffffff, tm1, 2));

            float mn0 = fmaxf(m0, tm0);
            float mn1 = fmaxf(m1, tm1);
            float corr0 = exp2f((m0 - mn0) * SC2);
            float corr1 = exp2f((m1 - mn1) * SC2);

            float p[8][4];
            float rs0 = 0.f, rs1 = 0.f;
            #pragma unroll
            for (int nc = 0; nc < 8; nc++) {
                p[nc][0] = exp2f((s[nc][0] - mn0) * SC2);
                p[nc][1] = exp2f((s[nc][1] - mn0) * SC2);
                p[nc][2] = exp2f((s[nc][2] - mn1) * SC2);
                p[nc][3] = exp2f((s[nc][3] - mn1) * SC2);
                rs0 += p[nc][0] + p[nc][1];
                rs1 += p[nc][2] + p[nc][3];
            }
            rs0 += __shfl_xor_sync(0xffffffff, rs0, 1);
            rs0 += __shfl_xor_sync(0xffffffff, rs0, 2);
            rs1 += __shfl_xor_sync(0xffffffff, rs1, 1);
            rs1 += __shfl_xor_sync(0xffffffff, rs1, 2);

            l0 = l0 * corr0 + rs0;
            l1 = l1 * corr1 + rs1;
            m0 = mn0; m1 = mn1;
            #pragma unroll
            for (int nc = 0; nc < 8; nc++) {
                o[nc][0] *= corr0; o[nc][1] *= corr0;
                o[nc][2] *= corr1; o[nc][3] *= corr1;
            }

            // ---- pack P to fp16 A-fragments ----
            uint32_t pf[4][4];
            #pragma unroll
            for (int kc = 0; kc < 4; kc++) {
                const int n0c = 2 * kc, n1c = 2 * kc + 1;
                pf[kc][0] = pack_h2(p[n0c][0], p[n0c][1]);
                pf[kc][1] = pack_h2(p[n0c][2], p[n0c][3]);
                pf[kc][2] = pack_h2(p[n1c][0], p[n1c][1]);
                pf[kc][3] = pack_h2(p[n1c][2], p[n1c][3]);
            }

            // ---- O += P @ V ----
            #pragma unroll
            for (int nc = 0; nc < 8; nc++) {
                uint32_t rowOff = (uint32_t)(nc * 8 + nR) * AT_ROWB + cS + kcS;
                uint32_t vh[4][2];
                ldsm_x4(vh[0][0], vh[0][1], vh[1][0], vh[1][1], VH + rowOff);
                ldsm_x4(vh[2][0], vh[2][1], vh[3][0], vh[3][1], VH + rowOff + 64);
                #pragma unroll
                for (int kc = 0; kc < 4; kc++)
                    mma_f16(o[nc][0], o[nc][1], o[nc][2], o[nc][3],
                            pf[kc][0], pf[kc][1], pf[kc][2], pf[kc][3],
                            vh[kc][0], vh[kc][1]);
            }
        }
        __syncthreads();
    }

    // ---- epilogue ----
    const float inv0 = 1.f / l0;
    const float inv1 = 1.f / l1;
    const size_t tok0 = (size_t)(b * L_ + q0 + wid * 16 + arow);
    #pragma unroll
    for (int nc = 0; nc < 8; nc++) {
        int col = h * HD_ + nc * 8 + acol * 2;
        *(uint32_t*)(out + tok0 * D_ + col)       = pack_h2(o[nc][0] * inv0, o[nc][1] * inv0);
        *(uint32_t*)(out + (tok0 + 8) * D_ + col) = pack_h2(o[nc][2] * inv1, o[nc][3] * inv1);
    }
}

// ---------------------------------------------------------------------------
extern "C" void kernel_launch(void* const* d_in, const int* in_sizes, int n_in,
                              void* d_out, int out_size)
{
    const float* x     = (const float*)d_in[0];
    const float* w_in  = (const float*)d_in[1];
    const float* b_in  = (const float*)d_in[2];
    const float* w_out = (const float*)d_in[3];
    const float* b_out = (const float*)d_in[4];
    float* y = (float*)d_out;

    __half *qkv, *vt, *x16, *winT, *woutT, *att;
    cudaGetSymbolAddress((void**)&qkv,   g_qkv);
    cudaGetSymbolAddress((void**)&vt,    g_vt);
    cudaGetSymbolAddress((void**)&x16,   g_x16);
    cudaGetSymbolAddress((void**)&winT,  g_winT);
    cudaGetSymbolAddress((void**)&woutT, g_woutT);
    cudaGetSymbolAddress((void**)&att,   g_att);

    static bool attr_set = false;
    if (!attr_set) {
        cudaFuncSetAttribute(gemm_mma_kernel<true>,  cudaFuncAttributeMaxDynamicSharedMemorySize, SMEMB);
        cudaFuncSetAttribute(gemm_mma_kernel<false>, cudaFuncAttributeMaxDynamicSharedMemorySize, SMEMB);
        cudaFuncSetAttribute(attn_mma_kernel, cudaFuncAttributeMaxDynamicSharedMemorySize, AT_SMEM);
        attr_set = true;
    }

    // prep
    convert_f16_kernel<<<4096, 256>>>(x, x16, M_ * D_);
    {
        dim3 g(E_ / 32, D_ / 32); dim3 blk(32, 32);
        transpose_f16_kernel<<<g, blk>>>(w_in, winT, D_, E_);
    }
    {
        dim3 g(D_ / 32, D_ / 32); dim3 blk(32, 32);
        transpose_f16_kernel<<<g, blk>>>(w_out, woutT, D_, D_);
    }

    // 1) QKV projection -> fp16
    {
        dim3 grid(E_ / 128, M_ / 128);
        gemm_mma_kernel<true><<<grid, 256, SMEMB>>>(
            x16, winT, b_in, nullptr, qkv, M_, E_, D_);
    }

    // 1b) transpose V region
    {
        dim3 g(L_ / 32, D_ / 32, B_); dim3 blk(32, 32);
        transpose_v_kernel<<<g, blk>>>(qkv, vt);
    }

    // 2) tensor-core causal flash attention
    {
        dim3 grid(L_ / 128, H_, B_);
        attn_mma_kernel<<<grid, 256, AT_SMEM>>>(qkv, vt, att);
    }

    // 3) output projection -> fp32 y
    {
        dim3 grid(D_ / 128, M_ / 128);
        gemm_mma_kernel<false><<<grid, 256, SMEMB>>>(
            att, woutT, b_out, y, nullptr, M_, D_, D_);
    }
}

// round 7
// speedup vs baseline: 9.3270x; 1.0567x over previous
#include <cuda_runtime.h>
#include <cuda_fp16.h>
#include <cstdint>

// ---------------------------------------------------------------------------
// Problem constants
// ---------------------------------------------------------------------------
#define B_   4
#define L_   2048
#define D_   1024
#define H_   16
#define HD_  64
#define E_   3072          // 3*D
#define M_   (B_ * L_)     // 8192 rows

// ---------------------------------------------------------------------------
// Scratch (device globals; no allocation allowed)
// ---------------------------------------------------------------------------
__device__ __half g_qkv[(size_t)M_ * E_];          // qkv fp16 [8192, 3072]
__device__ __half g_vt[(size_t)(B_*H_*HD_) * L_];  // V^T fp16 [4096, 2048]
__device__ __half g_x16[(size_t)M_ * D_];          // x fp16
__device__ __half g_winT[(size_t)E_ * D_];         // w_in^T  [3072,1024]
__device__ __half g_woutT[(size_t)D_ * D_];        // w_out^T [1024,1024]
__device__ __half g_att[(size_t)M_ * D_];          // attention out fp16

// ---------------------------------------------------------------------------
// Helpers
// ---------------------------------------------------------------------------
__device__ __forceinline__ uint32_t smem_u32(const void* p) {
    uint32_t a;
    asm("{ .reg .u64 t; cvta.to.shared.u64 t, %1; cvt.u32.u64 %0, t; }" : "=r"(a) : "l"(p));
    return a;
}

#define CP_ASYNC16(saddr, gptr) \
    asm volatile("cp.async.cg.shared.global [%0], [%1], 16;" :: "r"(saddr), "l"(gptr))
#define CP_COMMIT() asm volatile("cp.async.commit_group;" ::: "memory")
#define CP_WAIT(n)  asm volatile("cp.async.wait_group %0;" :: "n"(n) : "memory")

__device__ __forceinline__ void mma_f16(float& c0, float& c1, float& c2, float& c3,
                                        uint32_t a0, uint32_t a1, uint32_t a2, uint32_t a3,
                                        uint32_t b0, uint32_t b1) {
    asm volatile(
        "mma.sync.aligned.m16n8k16.row.col.f32.f16.f16.f32 "
        "{%0,%1,%2,%3}, {%4,%5,%6,%7}, {%8,%9}, {%0,%1,%2,%3};"
        : "+f"(c0), "+f"(c1), "+f"(c2), "+f"(c3)
        : "r"(a0), "r"(a1), "r"(a2), "r"(a3), "r"(b0), "r"(b1));
}

__device__ __forceinline__ void ldsm_x4(uint32_t& r0, uint32_t& r1, uint32_t& r2, uint32_t& r3,
                                        uint32_t addr) {
    asm volatile("ldmatrix.sync.aligned.m8n8.x4.shared.b16 {%0,%1,%2,%3}, [%4];"
                 : "=r"(r0), "=r"(r1), "=r"(r2), "=r"(r3) : "r"(addr));
}

__device__ __forceinline__ uint32_t pack_h2(float x, float y) {
    __half2 v = __floats2half2_rn(x, y);
    return *reinterpret_cast<uint32_t*>(&v);
}

// ---------------------------------------------------------------------------
// Prep kernels
// ---------------------------------------------------------------------------
__global__ void convert_f16_kernel(const float* __restrict__ src,
                                   __half* __restrict__ dst, int n)
{
    for (int i = blockIdx.x * blockDim.x + threadIdx.x; i < n; i += gridDim.x * blockDim.x)
        dst[i] = __float2half_rn(src[i]);
}

// src [K, N] row-major -> dst [N, K] fp16
__global__ void transpose_f16_kernel(const float* __restrict__ src,
                                     __half* __restrict__ dst, int K, int N)
{
    __shared__ float tile[32][33];
    int n0 = blockIdx.x * 32, k0 = blockIdx.y * 32;
    int tx = threadIdx.x, ty = threadIdx.y;
    tile[ty][tx] = src[(size_t)(k0 + ty) * N + n0 + tx];
    __syncthreads();
    dst[(size_t)(n0 + ty) * K + k0 + tx] = __float2half_rn(tile[tx][ty]);
}

// Transpose V region of qkv into [(b,h,d), l] layout.
__global__ void transpose_v_kernel(const __half* __restrict__ qkv,
                                   __half* __restrict__ vt)
{
    __shared__ __half t[32][33];
    int b  = blockIdx.z;
    int lt = blockIdx.x * 32;
    int ct = blockIdx.y * 32;
    int tx = threadIdx.x, ty = threadIdx.y;
    t[ty][tx] = qkv[(size_t)(b * L_ + lt + ty) * E_ + 2 * D_ + ct + tx];
    __syncthreads();
    vt[(size_t)(b * D_ + ct + ty) * L_ + lt + tx] = t[tx][ty];
}

// ---------------------------------------------------------------------------
// fp16 GEMM: C[M,N] = A[M,K] @ B[N,K]^T + bias[N]
// 128x128x64 tiles, 8 warps (2x4, warp 64x32), 3-stage ring, ONE barrier/iter.
// ---------------------------------------------------------------------------
#define BKG 64
#define ROWB 144                      // 64 fp16 = 128B + 16B pad
#define MATB (128 * ROWB)             // 18432
#define STAGEB (2 * MATB)             // A + B = 36864
#define NSTAGE 3
#define SMEMB (NSTAGE * STAGEB)       // 110592

template <bool OUT_HALF>
__global__ __launch_bounds__(256, 2) void gemm_mma_kernel(
    const __half* __restrict__ A, const __half* __restrict__ Bm,
    const float* __restrict__ bias, float* __restrict__ C,
    __half* __restrict__ Ch,
    int M, int N, int K)
{
    extern __shared__ char sm[];
    const int tid  = threadIdx.x;
    const int lane = tid & 31;
    const int wid  = tid >> 5;
    const int wm   = wid & 1;
    const int wn   = wid >> 1;
    const int row0 = blockIdx.y * 128;
    const int col0 = blockIdx.x * 128;
    const uint32_t smem_base = smem_u32(sm);

    float acc[4][4][4];
    #pragma unroll
    for (int i = 0; i < 4; i++)
        #pragma unroll
        for (int j = 0; j < 4; j++)
            #pragma unroll
            for (int c = 0; c < 4; c++) acc[i][j][c] = 0.f;

    const int nk = K / BKG;

    auto load_stage = [&](int i) {
        const int k0 = i * BKG;
        const uint32_t sbase = smem_base + (i % NSTAGE) * STAGEB;
        #pragma unroll
        for (int t = 0; t < 4; t++) {
            int c = tid + t * 256;
            int r = c >> 3, c8 = c & 7;
            uint32_t so = r * ROWB + c8 * 16;
            size_t ga = (size_t)(row0 + r) * K + k0 + c8 * 8;
            size_t gb = (size_t)(col0 + r) * K + k0 + c8 * 8;
            CP_ASYNC16(sbase + 0 * MATB + so, A + ga);
            CP_ASYNC16(sbase + 1 * MATB + so, Bm + gb);
        }
        CP_COMMIT();
    };

    load_stage(0);
    load_stage(1);

    const int lr8 = lane & 7;
    const int aRow = wm * 64 + lr8 + ((lane & 8) ? 8 : 0);
    const int aCS  = (lane & 16) ? 16 : 0;
    const int bRow = wn * 32 + ((lane & 16) ? 8 : 0) + lr8;
    const int bCS  = (lane & 8) ? 16 : 0;

    const int arow = (lane >> 2);
    const int acol = (lane & 3) * 2;

    for (int i = 0; i < nk; i++) {
        if (i + 1 < nk) { CP_WAIT(1); } else { CP_WAIT(0); }
        __syncthreads();
        if (i + 2 < nk) load_stage(i + 2);

        const uint32_t st = smem_base + (i % NSTAGE) * STAGEB;

        #pragma unroll
        for (int kk = 0; kk < 4; kk++) {
            const int kb = kk * 32;
            uint32_t ah[4][4], bh[2][4];
            #pragma unroll
            for (int im = 0; im < 4; im++)
                ldsm_x4(ah[im][0], ah[im][1], ah[im][2], ah[im][3],
                        st + 0 * MATB + (uint32_t)(aRow + im * 16) * ROWB + kb + aCS);
            #pragma unroll
            for (int inp = 0; inp < 2; inp++)
                ldsm_x4(bh[inp][0], bh[inp][1], bh[inp][2], bh[inp][3],
                        st + 1 * MATB + (uint32_t)(bRow + inp * 16) * ROWB + kb + bCS);
            #pragma unroll
            for (int im = 0; im < 4; im++)
                #pragma unroll
                for (int in = 0; in < 4; in++)
                    mma_f16(acc[im][in][0], acc[im][in][1], acc[im][in][2], acc[im][in][3],
                            ah[im][0], ah[im][1], ah[im][2], ah[im][3],
                            bh[in >> 1][(in & 1) * 2], bh[in >> 1][(in & 1) * 2 + 1]);
        }
    }

    #pragma unroll
    for (int im = 0; im < 4; im++) {
        int r = row0 + wm * 64 + im * 16 + arow;
        #pragma unroll
        for (int in = 0; in < 4; in++) {
            int cc = col0 + wn * 32 + in * 8 + acol;
            float2 b0 = *(const float2*)(bias + cc);
            float f0 = acc[im][in][0] + b0.x;
            float f1 = acc[im][in][1] + b0.y;
            float f2 = acc[im][in][2] + b0.x;
            float f3 = acc[im][in][3] + b0.y;
            if (OUT_HALF) {
                *(uint32_t*)(Ch + (size_t)r * N + cc)       = pack_h2(f0, f1);
                *(uint32_t*)(Ch + (size_t)(r + 8) * N + cc) = pack_h2(f2, f3);
            } else {
                *(float2*)(C + (size_t)r * N + cc)       = make_float2(f0, f1);
                *(float2*)(C + (size_t)(r + 8) * N + cc) = make_float2(f2, f3);
            }
        }
    }
}

// ---------------------------------------------------------------------------
// fp16 tensor-core causal flash attention. ONE barrier per kv tile.
// Block 256 thr (8 warps x 16 q-rows = 128 q-rows). kv tiles of 64, double buf.
// ---------------------------------------------------------------------------
#define AT_ROWB 144                       // 64 fp16 = 128B + 16B pad
#define AT_QBYTES (128 * AT_ROWB)         // 18432
#define AT_TBY (64 * AT_ROWB)             // 9216
#define AT_STAGEB (2 * AT_TBY)            // K + V = 18432
#define AT_SMEM (AT_QBYTES + 2 * AT_STAGEB)   // 55296

__global__ __launch_bounds__(256, 2) void attn_mma_kernel(
    const __half* __restrict__ qkv, const __half* __restrict__ vt,
    __half* __restrict__ out)
{
    extern __shared__ char sm[];
    const int tid  = threadIdx.x;
    const int lane = tid & 31;
    const int wid  = tid >> 5;
    const int qt = blockIdx.x, h = blockIdx.y, b = blockIdx.z;
    const int q0 = qt * 128;
    const uint32_t sb = smem_u32(sm);
    const int arow = lane >> 2;
    const int acol = lane & 3;
    const float SC2 = 0.18033688011f;   // 0.125 * log2(e)

    // ---- stage Q ----
    #pragma unroll
    for (int t = 0; t < 4; t++) {
        int c = tid + t * 256;
        int r = c >> 3, ch = c & 7;
        size_t g = (size_t)(b * L_ + q0 + r) * E_ + h * HD_ + ch * 8;
        CP_ASYNC16(sb + r * AT_ROWB + ch * 16, qkv + g);
    }
    CP_COMMIT();

    auto load_kv = [&](int t2) {
        const int k0 = t2 * 64;
        const uint32_t sbase = sb + AT_QBYTES + (t2 & 1) * AT_STAGEB;
        #pragma unroll
        for (int u = 0; u < 2; u++) {
            int c = tid + u * 256;
            int r = c >> 3, ch = c & 7;
            uint32_t so = r * AT_ROWB + ch * 16;
            size_t gk = (size_t)(b * L_ + k0 + r) * E_ + D_ + h * HD_ + ch * 8;
            CP_ASYNC16(sbase + so, qkv + gk);
            size_t gv = (size_t)((b * H_ + h) * HD_ + r) * L_ + k0 + ch * 8;
            CP_ASYNC16(sbase + AT_TBY + so, vt + gv);
        }
        CP_COMMIT();
    };

    load_kv(0);

    float o[8][4];
    #pragma unroll
    for (int i = 0; i < 8; i++)
        #pragma unroll
        for (int j = 0; j < 4; j++) o[i][j] = 0.f;
    float m0 = -1e30f, m1 = -1e30f, l0 = 0.f, l1 = 0.f;

    const int rg0 = q0 + wid * 16 + arow;
    const int rg1 = rg0 + 8;
    const int nt = 2 * qt + 2;

    const int nR  = lane & 7;
    const int kcS = (lane & 16) ? 32 : 0;
    const int cS  = (lane & 8) ? 16 : 0;

    uint32_t qf[4][4];
    bool qloaded = false;

    for (int t = 0; t < nt; t++) {
        CP_WAIT(0);
        __syncthreads();
        if (t + 1 < nt) load_kv(t + 1);

        if (!qloaded) {
            qloaded = true;
            const char* QH = sm;
            int r = wid * 16 + arow;
            #pragma unroll
            for (int kc = 0; kc < 4; kc++) {
                int colb = kc * 32 + acol * 4;
                qf[kc][0] = *(const uint32_t*)(QH + r * AT_ROWB + colb);
                qf[kc][1] = *(const uint32_t*)(QH + (r + 8) * AT_ROWB + colb);
                qf[kc][2] = *(const uint32_t*)(QH + r * AT_ROWB + colb + 16);
                qf[kc][3] = *(const uint32_t*)(QH + (r + 8) * AT_ROWB + colb + 16);
            }
        }

        const int k0 = t * 64;
        const uint32_t st = sb + AT_QBYTES + (t & 1) * AT_STAGEB;
        const uint32_t KH = st;
        const uint32_t VH = st + AT_TBY;

        const bool active = (k0 <= q0 + wid * 16 + 15);
        if (active) {
            // ---- S = Q @ K^T ----
            float s[8][4];
            #pragma unroll
            for (int i = 0; i < 8; i++)
                #pragma unroll
                for (int j = 0; j < 4; j++) s[i][j] = 0.f;

            #pragma unroll
            for (int nc = 0; nc < 8; nc++) {
                uint32_t rowOff = (uint32_t)(nc * 8 + nR) * AT_ROWB + cS + kcS;
                uint32_t bh[4][2];
                ldsm_x4(bh[0][0], bh[0][1], bh[1][0], bh[1][1], KH + rowOff);
                ldsm_x4(bh[2][0], bh[2][1], bh[3][0], bh[3][1], KH + rowOff + 64);
                #pragma unroll
                for (int kc = 0; kc < 4; kc++)
                    mma_f16(s[nc][0], s[nc][1], s[nc][2], s[nc][3],
                            qf[kc][0], qf[kc][1], qf[kc][2], qf[kc][3],
                            bh[kc][0], bh[kc][1]);
            }

            // ---- causal mask ----
            if (k0 + 63 > q0 + wid * 16) {
                #pragma unroll
                for (int nc = 0; nc < 8; nc++) {
                    int kbase = k0 + nc * 8 + acol * 2;
                    #pragma unroll
                    for (int e = 0; e < 2; e++) {
                        if (kbase + e > rg0) s[nc][e]     = -1e30f;
                        if (kbase + e > rg1) s[nc][2 + e] = -1e30f;
                    }
                }
            }

            // ---- online softmax ----
            float tm0 = -1e30f, tm1 = -1e30f;
            #pragma unroll
            for (int nc = 0; nc < 8; nc++) {
                tm0 = fmaxf(tm0, fmaxf(s[nc][0], s[nc][1]));
                tm1 = fmaxf(tm1, fmaxf(s[nc][2], s[nc][3]));
            }
            tm0 = fmaxf(tm0, __shfl_xor_sync(0xffffffff, tm0, 1));
            tm0 = fmaxf(tm0, __shfl_xor_sync(0xffffffff, tm0, 2));
            tm1 = fmaxf(tm1, __shfl_xor_sync(0xffffffff, tm1, 1));
            tm1 = fmaxf(tm1, __shfl_xor_sync(0xffffffff, tm1, 2));

            float mn0 = fmaxf(m0, tm0);
            float mn1 = fmaxf(m1, tm1);
            float corr0 = exp2f((m0 - mn0) * SC2);
            float corr1 = exp2f((m1 - mn1) * SC2);

            float p[8][4];
            float rs0 = 0.f, rs1 = 0.f;
            #pragma unroll
            for (int nc = 0; nc < 8; nc++) {
                p[nc][0] = exp2f((s[nc][0] - mn0) * SC2);
                p[nc][1] = exp2f((s[nc][1] - mn0) * SC2);
                p[nc][2] = exp2f((s[nc][2] - mn1) * SC2);
                p[nc][3] = exp2f((s[nc][3] - mn1) * SC2);
                rs0 += p[nc][0] + p[nc][1];
                rs1 += p[nc][2] + p[nc][3];
            }
            rs0 += __shfl_xor_sync(0xffffffff, rs0, 1);
            rs0 += __shfl_xor_sync(0xffffffff, rs0, 2);
            rs1 += __shfl_xor_sync(0xffffffff, rs1, 1);
            rs1 += __shfl_xor_sync(0xffffffff, rs1, 2);

            l0 = l0 * corr0 + rs0;
            l1 = l1 * corr1 + rs1;
            m0 = mn0; m1 = mn1;
            #pragma unroll
            for (int nc = 0; nc < 8; nc++) {
                o[nc][0] *= corr0; o[nc][1] *= corr0;
                o[nc][2] *= corr1; o[nc][3] *= corr1;
            }

            // ---- pack P to fp16 A-fragments ----
            uint32_t pf[4][4];
            #pragma unroll
            for (int kc = 0; kc < 4; kc++) {
                const int n0c = 2 * kc, n1c = 2 * kc + 1;
                pf[kc][0] = pack_h2(p[n0c][0], p[n0c][1]);
                pf[kc][1] = pack_h2(p[n0c][2], p[n0c][3]);
                pf[kc][2] = pack_h2(p[n1c][0], p[n1c][1]);
                pf[kc][3] = pack_h2(p[n1c][2], p[n1c][3]);
            }

            // ---- O += P @ V ----
            #pragma unroll
            for (int nc = 0; nc < 8; nc++) {
                uint32_t rowOff = (uint32_t)(nc * 8 + nR) * AT_ROWB + cS + kcS;
                uint32_t vh[4][2];
                ldsm_x4(vh[0][0], vh[0][1], vh[1][0], vh[1][1], VH + rowOff);
                ldsm_x4(vh[2][0], vh[2][1], vh[3][0], vh[3][1], VH + rowOff + 64);
                #pragma unroll
                for (int kc = 0; kc < 4; kc++)
                    mma_f16(o[nc][0], o[nc][1], o[nc][2], o[nc][3],
                            pf[kc][0], pf[kc][1], pf[kc][2], pf[kc][3],
                            vh[kc][0], vh[kc][1]);
            }
        }
    }

    // ---- epilogue ----
    const float inv0 = 1.f / l0;
    const float inv1 = 1.f / l1;
    const size_t tok0 = (size_t)(b * L_ + q0 + wid * 16 + arow);
    #pragma unroll
    for (int nc = 0; nc < 8; nc++) {
        int col = h * HD_ + nc * 8 + acol * 2;
        *(uint32_t*)(out + tok0 * D_ + col)       = pack_h2(o[nc][0] * inv0, o[nc][1] * inv0);
        *(uint32_t*)(out + (tok0 + 8) * D_ + col) = pack_h2(o[nc][2] * inv1, o[nc][3] * inv1);
    }
}

// ---------------------------------------------------------------------------
extern "C" void kernel_launch(void* const* d_in, const int* in_sizes, int n_in,
                              void* d_out, int out_size)
{
    const float* x     = (const float*)d_in[0];
    const float* w_in  = (const float*)d_in[1];
    const float* b_in  = (const float*)d_in[2];
    const float* w_out = (const float*)d_in[3];
    const float* b_out = (const float*)d_in[4];
    float* y = (float*)d_out;

    __half *qkv, *vt, *x16, *winT, *woutT, *att;
    cudaGetSymbolAddress((void**)&qkv,   g_qkv);
    cudaGetSymbolAddress((void**)&vt,    g_vt);
    cudaGetSymbolAddress((void**)&x16,   g_x16);
    cudaGetSymbolAddress((void**)&winT,  g_winT);
    cudaGetSymbolAddress((void**)&woutT, g_woutT);
    cudaGetSymbolAddress((void**)&att,   g_att);

    static bool attr_set = false;
    if (!attr_set) {
        cudaFuncSetAttribute(gemm_mma_kernel<true>,  cudaFuncAttributeMaxDynamicSharedMemorySize, SMEMB);
        cudaFuncSetAttribute(gemm_mma_kernel<false>, cudaFuncAttributeMaxDynamicSharedMemorySize, SMEMB);
        cudaFuncSetAttribute(attn_mma_kernel, cudaFuncAttributeMaxDynamicSharedMemorySize, AT_SMEM);
        attr_set = true;
    }

    // prep
    convert_f16_kernel<<<4096, 256>>>(x, x16, M_ * D_);
    {
        dim3 g(E_ / 32, D_ / 32); dim3 blk(32, 32);
        transpose_f16_kernel<<<g, blk>>>(w_in, winT, D_, E_);
    }
    {
        dim3 g(D_ / 32, D_ / 32); dim3 blk(32, 32);
        transpose_f16_kernel<<<g, blk>>>(w_out, woutT, D_, D_);
    }

    // 1) QKV projection -> fp16
    {
        dim3 grid(E_ / 128, M_ / 128);
        gemm_mma_kernel<true><<<grid, 256, SMEMB>>>(
            x16, winT, b_in, nullptr, qkv, M_, E_, D_);
    }

    // 1b) transpose V region
    {
        dim3 g(L_ / 32, D_ / 32, B_); dim3 blk(32, 32);
        transpose_v_kernel<<<g, blk>>>(qkv, vt);
    }

    // 2) tensor-core causal flash attention
    {
        dim3 grid(L_ / 128, H_, B_);
        attn_mma_kernel<<<grid, 256, AT_SMEM>>>(qkv, vt, att);
    }

    // 3) output projection -> fp32 y
    {
        dim3 grid(D_ / 128, M_ / 128);
        gemm_mma_kernel<false><<<grid, 256, SMEMB>>>(
            att, woutT, b_out, y, nullptr, M_, D_, D_);
    }
}

// round 8
// speedup vs baseline: 10.0918x; 1.0820x over previous
#include <cuda_runtime.h>
#include <cuda_fp16.h>
#include <cstdint>

// ---------------------------------------------------------------------------
// Problem constants
// ---------------------------------------------------------------------------
#define B_   4
#define L_   2048
#define D_   1024
#define H_   16
#define HD_  64
#define E_   3072          // 3*D
#define M_   (B_ * L_)     // 8192 rows

// ---------------------------------------------------------------------------
// Scratch (device globals; no allocation allowed)
// ---------------------------------------------------------------------------
__device__ __half g_qkv[(size_t)M_ * E_];          // qkv fp16 [8192, 3072]
__device__ __half g_x16[(size_t)M_ * D_];          // x fp16
__device__ __half g_winT[(size_t)E_ * D_];         // w_in^T  [3072,1024]
__device__ __half g_woutT[(size_t)D_ * D_];        // w_out^T [1024,1024]
__device__ __half g_att[(size_t)M_ * D_];          // attention out fp16

// ---------------------------------------------------------------------------
// Helpers
// ---------------------------------------------------------------------------
__device__ __forceinline__ uint32_t smem_u32(const void* p) {
    uint32_t a;
    asm("{ .reg .u64 t; cvta.to.shared.u64 t, %1; cvt.u32.u64 %0, t; }" : "=r"(a) : "l"(p));
    return a;
}

#define CP_ASYNC16(saddr, gptr) \
    asm volatile("cp.async.cg.shared.global [%0], [%1], 16;" :: "r"(saddr), "l"(gptr))
#define CP_COMMIT() asm volatile("cp.async.commit_group;" ::: "memory")
#define CP_WAIT(n)  asm volatile("cp.async.wait_group %0;" :: "n"(n) : "memory")

__device__ __forceinline__ void mma_f16(float& c0, float& c1, float& c2, float& c3,
                                        uint32_t a0, uint32_t a1, uint32_t a2, uint32_t a3,
                                        uint32_t b0, uint32_t b1) {
    asm volatile(
        "mma.sync.aligned.m16n8k16.row.col.f32.f16.f16.f32 "
        "{%0,%1,%2,%3}, {%4,%5,%6,%7}, {%8,%9}, {%0,%1,%2,%3};"
        : "+f"(c0), "+f"(c1), "+f"(c2), "+f"(c3)
        : "r"(a0), "r"(a1), "r"(a2), "r"(a3), "r"(b0), "r"(b1));
}

__device__ __forceinline__ void ldsm_x4(uint32_t& r0, uint32_t& r1, uint32_t& r2, uint32_t& r3,
                                        uint32_t addr) {
    asm volatile("ldmatrix.sync.aligned.m8n8.x4.shared.b16 {%0,%1,%2,%3}, [%4];"
                 : "=r"(r0), "=r"(r1), "=r"(r2), "=r"(r3) : "r"(addr));
}

__device__ __forceinline__ void ldsm_x4_trans(uint32_t& r0, uint32_t& r1, uint32_t& r2, uint32_t& r3,
                                              uint32_t addr) {
    asm volatile("ldmatrix.sync.aligned.m8n8.x4.trans.shared.b16 {%0,%1,%2,%3}, [%4];"
                 : "=r"(r0), "=r"(r1), "=r"(r2), "=r"(r3) : "r"(addr));
}

__device__ __forceinline__ uint32_t pack_h2(float x, float y) {
    __half2 v = __floats2half2_rn(x, y);
    return *reinterpret_cast<uint32_t*>(&v);
}

// ---------------------------------------------------------------------------
// Prep kernels
// ---------------------------------------------------------------------------
__global__ void convert_f16_kernel(const float* __restrict__ src,
                                   __half* __restrict__ dst, int n4)
{
    int i = blockIdx.x * blockDim.x + threadIdx.x;
    if (i < n4) {
        float4 v = ((const float4*)src)[i];
        uint2 o;
        o.x = pack_h2(v.x, v.y);
        o.y = pack_h2(v.z, v.w);
        ((uint2*)dst)[i] = o;
    }
}

// src [K, N] row-major -> dst [N, K] fp16
__global__ void transpose_f16_kernel(const float* __restrict__ src,
                                     __half* __restrict__ dst, int K, int N)
{
    __shared__ float tile[32][33];
    int n0 = blockIdx.x * 32, k0 = blockIdx.y * 32;
    int tx = threadIdx.x, ty = threadIdx.y;
    tile[ty][tx] = src[(size_t)(k0 + ty) * N + n0 + tx];
    __syncthreads();
    dst[(size_t)(n0 + ty) * K + k0 + tx] = __float2half_rn(tile[tx][ty]);
}

// ---------------------------------------------------------------------------
// fp16 GEMM: C[M,N] = A[M,K] @ B[N,K]^T + bias[N]
// 128x128x64 tiles, 8 warps (2x4, warp 64x32), 3-stage ring, one barrier/iter,
// register-level fragment double-buffering across the 4 k16 steps.
// ---------------------------------------------------------------------------
#define BKG 64
#define ROWB 144                      // 64 fp16 = 128B + 16B pad
#define MATB (128 * ROWB)             // 18432
#define STAGEB (2 * MATB)             // A + B = 36864
#define NSTAGE 3
#define SMEMB (NSTAGE * STAGEB)       // 110592

template <bool OUT_HALF>
__global__ __launch_bounds__(256, 2) void gemm_mma_kernel(
    const __half* __restrict__ A, const __half* __restrict__ Bm,
    const float* __restrict__ bias, float* __restrict__ C,
    __half* __restrict__ Ch,
    int M, int N, int K)
{
    extern __shared__ char sm[];
    const int tid  = threadIdx.x;
    const int lane = tid & 31;
    const int wid  = tid >> 5;
    const int wm   = wid & 1;
    const int wn   = wid >> 1;
    const int row0 = blockIdx.y * 128;
    const int col0 = blockIdx.x * 128;
    const uint32_t smem_base = smem_u32(sm);

    float acc[4][4][4];
    #pragma unroll
    for (int i = 0; i < 4; i++)
        #pragma unroll
        for (int j = 0; j < 4; j++)
            #pragma unroll
            for (int c = 0; c < 4; c++) acc[i][j][c] = 0.f;

    const int nk = K / BKG;

    auto load_stage = [&](int i) {
        const int k0 = i * BKG;
        const uint32_t sbase = smem_base + (i % NSTAGE) * STAGEB;
        #pragma unroll
        for (int t = 0; t < 4; t++) {
            int c = tid + t * 256;
            int r = c >> 3, c8 = c & 7;
            uint32_t so = r * ROWB + c8 * 16;
            size_t ga = (size_t)(row0 + r) * K + k0 + c8 * 8;
            size_t gb = (size_t)(col0 + r) * K + k0 + c8 * 8;
            CP_ASYNC16(sbase + 0 * MATB + so, A + ga);
            CP_ASYNC16(sbase + 1 * MATB + so, Bm + gb);
        }
        CP_COMMIT();
    };

    load_stage(0);
    load_stage(1);

    const int lr8 = lane & 7;
    const int aRow = wm * 64 + lr8 + ((lane & 8) ? 8 : 0);
    const int aCS  = (lane & 16) ? 16 : 0;
    const int bRow = wn * 32 + ((lane & 16) ? 8 : 0) + lr8;
    const int bCS  = (lane & 8) ? 16 : 0;

    const int arow = (lane >> 2);
    const int acol = (lane & 3) * 2;

    uint32_t ah[2][4][4], bh[2][2][4];

    auto load_frags = [&](uint32_t st, int kb, int buf) {
        #pragma unroll
        for (int im = 0; im < 4; im++)
            ldsm_x4(ah[buf][im][0], ah[buf][im][1], ah[buf][im][2], ah[buf][im][3],
                    st + 0 * MATB + (uint32_t)(aRow + im * 16) * ROWB + kb + aCS);
        #pragma unroll
        for (int inp = 0; inp < 2; inp++)
            ldsm_x4(bh[buf][inp][0], bh[buf][inp][1], bh[buf][inp][2], bh[buf][inp][3],
                    st + 1 * MATB + (uint32_t)(bRow + inp * 16) * ROWB + kb + bCS);
    };

    for (int i = 0; i < nk; i++) {
        if (i + 1 < nk) { CP_WAIT(1); } else { CP_WAIT(0); }
        __syncthreads();
        if (i + 2 < nk) load_stage(i + 2);

        const uint32_t st = smem_base + (i % NSTAGE) * STAGEB;

        load_frags(st, 0, 0);
        #pragma unroll
        for (int kk = 0; kk < 4; kk++) {
            const int cur = kk & 1;
            if (kk < 3) load_frags(st, (kk + 1) * 32, cur ^ 1);
            #pragma unroll
            for (int im = 0; im < 4; im++)
                #pragma unroll
                for (int in = 0; in < 4; in++)
                    mma_f16(acc[im][in][0], acc[im][in][1], acc[im][in][2], acc[im][in][3],
                            ah[cur][im][0], ah[cur][im][1], ah[cur][im][2], ah[cur][im][3],
                            bh[cur][in >> 1][(in & 1) * 2], bh[cur][in >> 1][(in & 1) * 2 + 1]);
        }
    }

    #pragma unroll
    for (int im = 0; im < 4; im++) {
        int r = row0 + wm * 64 + im * 16 + arow;
        #pragma unroll
        for (int in = 0; in < 4; in++) {
            int cc = col0 + wn * 32 + in * 8 + acol;
            float2 b0 = *(const float2*)(bias + cc);
            float f0 = acc[im][in][0] + b0.x;
            float f1 = acc[im][in][1] + b0.y;
            float f2 = acc[im][in][2] + b0.x;
            float f3 = acc[im][in][3] + b0.y;
            if (OUT_HALF) {
                *(uint32_t*)(Ch + (size_t)r * N + cc)       = pack_h2(f0, f1);
                *(uint32_t*)(Ch + (size_t)(r + 8) * N + cc) = pack_h2(f2, f3);
            } else {
                *(float2*)(C + (size_t)r * N + cc)       = make_float2(f0, f1);
                *(float2*)(C + (size_t)(r + 8) * N + cc) = make_float2(f2, f3);
            }
        }
    }
}

// ---------------------------------------------------------------------------
// fp16 tensor-core causal flash attention.
// V loaded row-major straight from qkv; B-fragments built with ldmatrix.trans.
// Block 256 thr (8 warps x 16 q-rows = 128 q-rows). kv tiles of 64, double buf.
// ---------------------------------------------------------------------------
#define AT_ROWB 144                       // 64 fp16 = 128B + 16B pad
#define AT_QBYTES (128 * AT_ROWB)         // 18432
#define AT_TBY (64 * AT_ROWB)             // 9216
#define AT_STAGEB (2 * AT_TBY)            // K + V = 18432
#define AT_SMEM (AT_QBYTES + 2 * AT_STAGEB)   // 55296

__global__ __launch_bounds__(256, 2) void attn_mma_kernel(
    const __half* __restrict__ qkv, __half* __restrict__ out)
{
    extern __shared__ char sm[];
    const int tid  = threadIdx.x;
    const int lane = tid & 31;
    const int wid  = tid >> 5;
    const int qt = blockIdx.x, h = blockIdx.y, b = blockIdx.z;
    const int q0 = qt * 128;
    const uint32_t sb = smem_u32(sm);
    const int arow = lane >> 2;
    const int acol = lane & 3;
    const float SC2 = 0.18033688011f;   // 0.125 * log2(e)

    // ---- stage Q ----
    #pragma unroll
    for (int t = 0; t < 4; t++) {
        int c = tid + t * 256;
        int r = c >> 3, ch = c & 7;
        size_t g = (size_t)(b * L_ + q0 + r) * E_ + h * HD_ + ch * 8;
        CP_ASYNC16(sb + r * AT_ROWB + ch * 16, qkv + g);
    }
    CP_COMMIT();

    // K and V tiles come from the SAME qkv rows (offsets D_ and 2*D_).
    auto load_kv = [&](int t2) {
        const int k0 = t2 * 64;
        const uint32_t sbase = sb + AT_QBYTES + (t2 & 1) * AT_STAGEB;
        #pragma unroll
        for (int u = 0; u < 2; u++) {
            int c = tid + u * 256;
            int r = c >> 3, ch = c & 7;
            uint32_t so = r * AT_ROWB + ch * 16;
            size_t gk = (size_t)(b * L_ + k0 + r) * E_ + D_ + h * HD_ + ch * 8;
            CP_ASYNC16(sbase + so, qkv + gk);              // K rows
            CP_ASYNC16(sbase + AT_TBY + so, qkv + gk + D_); // V rows
        }
        CP_COMMIT();
    };

    load_kv(0);

    float o[8][4];
    #pragma unroll
    for (int i = 0; i < 8; i++)
        #pragma unroll
        for (int j = 0; j < 4; j++) o[i][j] = 0.f;
    float m0 = -1e30f, m1 = -1e30f, l0 = 0.f, l1 = 0.f;

    const int rg0 = q0 + wid * 16 + arow;
    const int rg1 = rg0 + 8;
    const int nt = 2 * qt + 2;

    // K (non-trans) fragment address parts
    const int nR  = lane & 7;
    const int kcS = (lane & 16) ? 32 : 0;
    const int cS  = (lane & 8) ? 16 : 0;
    // V (trans) fragment address part: lane group g = kv sub-block
    const uint32_t vRowOff = (uint32_t)(((lane >> 3) * 8) + (lane & 7)) * AT_ROWB;

    uint32_t qf[4][4];
    bool qloaded = false;

    for (int t = 0; t < nt; t++) {
        CP_WAIT(0);
        __syncthreads();
        if (t + 1 < nt) load_kv(t + 1);

        if (!qloaded) {
            qloaded = true;
            const char* QH = sm;
            int r = wid * 16 + arow;
            #pragma unroll
            for (int kc = 0; kc < 4; kc++) {
                int colb = kc * 32 + acol * 4;
                qf[kc][0] = *(const uint32_t*)(QH + r * AT_ROWB + colb);
                qf[kc][1] = *(const uint32_t*)(QH + (r + 8) * AT_ROWB + colb);
                qf[kc][2] = *(const uint32_t*)(QH + r * AT_ROWB + colb + 16);
                qf[kc][3] = *(const uint32_t*)(QH + (r + 8) * AT_ROWB + colb + 16);
            }
        }

        const int k0 = t * 64;
        const uint32_t st = sb + AT_QBYTES + (t & 1) * AT_STAGEB;
        const uint32_t KH = st;
        const uint32_t VH = st + AT_TBY;

        const bool active = (k0 <= q0 + wid * 16 + 15);
        if (active) {
            // ---- S = Q @ K^T ----
            float s[8][4];
            #pragma unroll
            for (int i = 0; i < 8; i++)
                #pragma unroll
                for (int j = 0; j < 4; j++) s[i][j] = 0.f;

            #pragma unroll
            for (int nc = 0; nc < 8; nc++) {
                uint32_t rowOff = (uint32_t)(nc * 8 + nR) * AT_ROWB + cS + kcS;
                uint32_t bhf[4][2];
                ldsm_x4(bhf[0][0], bhf[0][1], bhf[1][0], bhf[1][1], KH + rowOff);
                ldsm_x4(bhf[2][0], bhf[2][1], bhf[3][0], bhf[3][1], KH + rowOff + 64);
                #pragma unroll
                for (int kc = 0; kc < 4; kc++)
                    mma_f16(s[nc][0], s[nc][1], s[nc][2], s[nc][3],
                            qf[kc][0], qf[kc][1], qf[kc][2], qf[kc][3],
                            bhf[kc][0], bhf[kc][1]);
            }

            // ---- causal mask ----
            if (k0 + 63 > q0 + wid * 16) {
                #pragma unroll
                for (int nc = 0; nc < 8; nc++) {
                    int kbase = k0 + nc * 8 + acol * 2;
                    #pragma unroll
                    for (int e = 0; e < 2; e++) {
                        if (kbase + e > rg0) s[nc][e]     = -1e30f;
                        if (kbase + e > rg1) s[nc][2 + e] = -1e30f;
                    }
                }
            }

            // ---- online softmax ----
            float tm0 = -1e30f, tm1 = -1e30f;
            #pragma unroll
            for (int nc = 0; nc < 8; nc++) {
                tm0 = fmaxf(tm0, fmaxf(s[nc][0], s[nc][1]));
                tm1 = fmaxf(tm1, fmaxf(s[nc][2], s[nc][3]));
            }
            tm0 = fmaxf(tm0, __shfl_xor_sync(0xffffffff, tm0, 1));
            tm0 = fmaxf(tm0, __shfl_xor_sync(0xffffffff, tm0, 2));
            tm1 = fmaxf(tm1, __shfl_xor_sync(0xffffffff, tm1, 1));
            tm1 = fmaxf(tm1, __shfl_xor_sync(0xffffffff, tm1, 2));

            float mn0 = fmaxf(m0, tm0);
            float mn1 = fmaxf(m1, tm1);
            float corr0 = exp2f((m0 - mn0) * SC2);
            float corr1 = exp2f((m1 - mn1) * SC2);

            float p[8][4];
            float rs0 = 0.f, rs1 = 0.f;
            #pragma unroll
            for (int nc = 0; nc < 8; nc++) {
                p[nc][0] = exp2f((s[nc][0] - mn0) * SC2);
                p[nc][1] = exp2f((s[nc][1] - mn0) * SC2);
                p[nc][2] = exp2f((s[nc][2] - mn1) * SC2);
                p[nc][3] = exp2f((s[nc][3] - mn1) * SC2);
                rs0 += p[nc][0] + p[nc][1];
                rs1 += p[nc][2] + p[nc][3];
            }
            rs0 += __shfl_xor_sync(0xffffffff, rs0, 1);
            rs0 += __shfl_xor_sync(0xffffffff, rs0, 2);
            rs1 += __shfl_xor_sync(0xffffffff, rs1, 1);
            rs1 += __shfl_xor_sync(0xffffffff, rs1, 2);

            l0 = l0 * corr0 + rs0;
            l1 = l1 * corr1 + rs1;
            m0 = mn0; m1 = mn1;
            #pragma unroll
            for (int nc = 0; nc < 8; nc++) {
                o[nc][0] *= corr0; o[nc][1] *= corr0;
                o[nc][2] *= corr1; o[nc][3] *= corr1;
            }

            // ---- pack P to fp16 A-fragments ----
            uint32_t pf[4][4];
            #pragma unroll
            for (int kc = 0; kc < 4; kc++) {
                const int n0c = 2 * kc, n1c = 2 * kc + 1;
                pf[kc][0] = pack_h2(p[n0c][0], p[n0c][1]);
                pf[kc][1] = pack_h2(p[n0c][2], p[n0c][3]);
                pf[kc][2] = pack_h2(p[n1c][0], p[n1c][1]);
                pf[kc][3] = pack_h2(p[n1c][2], p[n1c][3]);
            }

            // ---- O += P @ V (V via ldmatrix.trans, nc = d-block) ----
            #pragma unroll
            for (int nc = 0; nc < 8; nc++) {
                uint32_t vb[4][2];
                uint32_t base = VH + vRowOff + nc * 16;
                ldsm_x4_trans(vb[0][0], vb[0][1], vb[1][0], vb[1][1], base);
                ldsm_x4_trans(vb[2][0], vb[2][1], vb[3][0], vb[3][1], base + 32 * AT_ROWB);
                #pragma unroll
                for (int kc = 0; kc < 4; kc++)
                    mma_f16(o[nc][0], o[nc][1], o[nc][2], o[nc][3],
                            pf[kc][0], pf[kc][1], pf[kc][2], pf[kc][3],
                            vb[kc][0], vb[kc][1]);
            }
        }
    }

    // ---- epilogue ----
    const float inv0 = 1.f / l0;
    const float inv1 = 1.f / l1;
    const size_t tok0 = (size_t)(b * L_ + q0 + wid * 16 + arow);
    #pragma unroll
    for (int nc = 0; nc < 8; nc++) {
        int col = h * HD_ + nc * 8 + acol * 2;
        *(uint32_t*)(out + tok0 * D_ + col)       = pack_h2(o[nc][0] * inv0, o[nc][1] * inv0);
        *(uint32_t*)(out + (tok0 + 8) * D_ + col) = pack_h2(o[nc][2] * inv1, o[nc][3] * inv1);
    }
}

// ---------------------------------------------------------------------------
extern "C" void kernel_launch(void* const* d_in, const int* in_sizes, int n_in,
                              void* d_out, int out_size)
{
    const float* x     = (const float*)d_in[0];
    const float* w_in  = (const float*)d_in[1];
    const float* b_in  = (const float*)d_in[2];
    const float* w_out = (const float*)d_in[3];
    const float* b_out = (const float*)d_in[4];
    float* y = (float*)d_out;

    __half *qkv, *x16, *winT, *woutT, *att;
    cudaGetSymbolAddress((void**)&qkv,   g_qkv);
    cudaGetSymbolAddress((void**)&x16,   g_x16);
    cudaGetSymbolAddress((void**)&winT,  g_winT);
    cudaGetSymbolAddress((void**)&woutT, g_woutT);
    cudaGetSymbolAddress((void**)&att,   g_att);

    static bool attr_set = false;
    if (!attr_set) {
        cudaFuncSetAttribute(gemm_mma_kernel<true>,  cudaFuncAttributeMaxDynamicSharedMemorySize, SMEMB);
        cudaFuncSetAttribute(gemm_mma_kernel<false>, cudaFuncAttributeMaxDynamicSharedMemorySize, SMEMB);
        cudaFuncSetAttribute(attn_mma_kernel, cudaFuncAttributeMaxDynamicSharedMemorySize, AT_SMEM);
        attr_set = true;
    }

    // prep
    convert_f16_kernel<<<(M_ * D_ / 4 + 255) / 256, 256>>>(x, x16, M_ * D_ / 4);
    {
        dim3 g(E_ / 32, D_ / 32); dim3 blk(32, 32);
        transpose_f16_kernel<<<g, blk>>>(w_in, winT, D_, E_);
    }
    {
        dim3 g(D_ / 32, D_ / 32); dim3 blk(32, 32);
        transpose_f16_kernel<<<g, blk>>>(w_out, woutT, D_, D_);
    }

    // 1) QKV projection -> fp16
    {
        dim3 grid(E_ / 128, M_ / 128);
        gemm_mma_kernel<true><<<grid, 256, SMEMB>>>(
            x16, winT, b_in, nullptr, qkv, M_, E_, D_);
    }

    // 2) tensor-core causal flash attention (V transposed in-register)
    {
        dim3 grid(L_ / 128, H_, B_);
        attn_mma_kernel<<<grid, 256, AT_SMEM>>>(qkv, att);
    }

    // 3) output projection -> fp32 y
    {
        dim3 grid(D_ / 128, M_ / 128);
        gemm_mma_kernel<false><<<grid, 256, SMEMB>>>(
            att, woutT, b_out, y, nullptr, M_, D_, D_);
    }
}

// round 9
// speedup vs baseline: 10.1157x; 1.0024x over previous
#include <cuda_runtime.h>
#include <cuda_fp16.h>
#include <cstdint>

// ---------------------------------------------------------------------------
// Problem constants
// ---------------------------------------------------------------------------
#define B_   4
#define L_   2048
#define D_   1024
#define H_   16
#define HD_  64
#define E_   3072          // 3*D
#define M_   (B_ * L_)     // 8192 rows

// ---------------------------------------------------------------------------
// Scratch (device globals; no allocation allowed)
// ---------------------------------------------------------------------------
__device__ __half g_qkv[(size_t)M_ * E_];     // qkv fp16 [8192, 3072]
__device__ __half g_x16[(size_t)M_ * D_];     // x fp16
__device__ __half g_win16[(size_t)D_ * E_];   // w_in  fp16 [K=1024, N=3072] row-major
__device__ __half g_wout16[(size_t)D_ * D_];  // w_out fp16 [K=1024, N=1024] row-major
__device__ __half g_att[(size_t)M_ * D_];     // attention out fp16

// ---------------------------------------------------------------------------
// Helpers
// ---------------------------------------------------------------------------
__device__ __forceinline__ uint32_t smem_u32(const void* p) {
    uint32_t a;
    asm("{ .reg .u64 t; cvta.to.shared.u64 t, %1; cvt.u32.u64 %0, t; }" : "=r"(a) : "l"(p));
    return a;
}

#define CP_ASYNC16(saddr, gptr) \
    asm volatile("cp.async.cg.shared.global [%0], [%1], 16;" :: "r"(saddr), "l"(gptr))
#define CP_COMMIT() asm volatile("cp.async.commit_group;" ::: "memory")
#define CP_WAIT(n)  asm volatile("cp.async.wait_group %0;" :: "n"(n) : "memory")

__device__ __forceinline__ void mma_f16(float& c0, float& c1, float& c2, float& c3,
                                        uint32_t a0, uint32_t a1, uint32_t a2, uint32_t a3,
                                        uint32_t b0, uint32_t b1) {
    asm volatile(
        "mma.sync.aligned.m16n8k16.row.col.f32.f16.f16.f32 "
        "{%0,%1,%2,%3}, {%4,%5,%6,%7}, {%8,%9}, {%0,%1,%2,%3};"
        : "+f"(c0), "+f"(c1), "+f"(c2), "+f"(c3)
        : "r"(a0), "r"(a1), "r"(a2), "r"(a3), "r"(b0), "r"(b1));
}

__device__ __forceinline__ void ldsm_x4(uint32_t& r0, uint32_t& r1, uint32_t& r2, uint32_t& r3,
                                        uint32_t addr) {
    asm volatile("ldmatrix.sync.aligned.m8n8.x4.shared.b16 {%0,%1,%2,%3}, [%4];"
                 : "=r"(r0), "=r"(r1), "=r"(r2), "=r"(r3) : "r"(addr));
}

__device__ __forceinline__ void ldsm_x4_trans(uint32_t& r0, uint32_t& r1, uint32_t& r2, uint32_t& r3,
                                              uint32_t addr) {
    asm volatile("ldmatrix.sync.aligned.m8n8.x4.trans.shared.b16 {%0,%1,%2,%3}, [%4];"
                 : "=r"(r0), "=r"(r1), "=r"(r2), "=r"(r3) : "r"(addr));
}

__device__ __forceinline__ uint32_t pack_h2(float x, float y) {
    __half2 v = __floats2half2_rn(x, y);
    return *reinterpret_cast<uint32_t*>(&v);
}

// ---------------------------------------------------------------------------
// Prep: vectorized fp32 -> fp16 convert (same layout)
// ---------------------------------------------------------------------------
__global__ void convert_f16_kernel(const float* __restrict__ src,
                                   __half* __restrict__ dst, int n4)
{
    int i = blockIdx.x * blockDim.x + threadIdx.x;
    if (i < n4) {
        float4 v = ((const float4*)src)[i];
        uint2 o;
        o.x = pack_h2(v.x, v.y);
        o.y = pack_h2(v.z, v.w);
        ((uint2*)dst)[i] = o;
    }
}

// ---------------------------------------------------------------------------
// fp16 GEMM: C[M,N] = A[M,K] @ W[K,N] + bias[N]   (W row-major, trans-ldmatrix)
// 128x128x64 tiles, 8 warps (2x4, warp 64x32), 3-stage ring, one barrier/iter.
// ---------------------------------------------------------------------------
#define BKG 64
#define A_ROWB 144                    // 64 fp16 = 128B + 16B pad
#define A_MATB (128 * A_ROWB)         // 18432
#define B_ROWB 272                    // 128 fp16 = 256B + 16B pad
#define B_MATB (64 * B_ROWB)          // 17408
#define STAGEB (A_MATB + B_MATB)      // 35840
#define NSTAGE 3
#define SMEMB (NSTAGE * STAGEB)       // 107520

template <bool OUT_HALF>
__global__ __launch_bounds__(256, 2) void gemm_mma_kernel(
    const __half* __restrict__ A, const __half* __restrict__ W,
    const float* __restrict__ bias, float* __restrict__ C,
    __half* __restrict__ Ch,
    int M, int N, int K)
{
    extern __shared__ char sm[];
    const int tid  = threadIdx.x;
    const int lane = tid & 31;
    const int wid  = tid >> 5;
    const int wm   = wid & 1;
    const int wn   = wid >> 1;
    const int row0 = blockIdx.y * 128;
    const int col0 = blockIdx.x * 128;
    const uint32_t smem_base = smem_u32(sm);

    float acc[4][4][4];
    #pragma unroll
    for (int i = 0; i < 4; i++)
        #pragma unroll
        for (int j = 0; j < 4; j++)
            #pragma unroll
            for (int c = 0; c < 4; c++) acc[i][j][c] = 0.f;

    const int nk = K / BKG;

    auto load_stage = [&](int i) {
        const int k0 = i * BKG;
        const uint32_t sbase = smem_base + (i % NSTAGE) * STAGEB;
        // A tile: 128 rows x 128B (8 chunks/row), 1024 chunks, 4/thread
        #pragma unroll
        for (int t = 0; t < 4; t++) {
            int c = tid + t * 256;
            int r = c >> 3, c8 = c & 7;
            size_t ga = (size_t)(row0 + r) * K + k0 + c8 * 8;
            CP_ASYNC16(sbase + r * A_ROWB + c8 * 16, A + ga);
        }
        // W tile: 64 k-rows x 256B (16 chunks/row), 1024 chunks, 4/thread
        #pragma unroll
        for (int t = 0; t < 4; t++) {
            int c = tid + t * 256;
            int r = c >> 4, c16 = c & 15;
            size_t gw = (size_t)(k0 + r) * N + col0 + c16 * 8;
            CP_ASYNC16(sbase + A_MATB + r * B_ROWB + c16 * 16, W + gw);
        }
        CP_COMMIT();
    };

    load_stage(0);
    load_stage(1);

    const int lr8 = lane & 7;
    const int aRow = wm * 64 + lr8 + ((lane & 8) ? 8 : 0);
    const int aCS  = (lane & 16) ? 16 : 0;
    const int arow = (lane >> 2);
    const int acol = (lane & 3) * 2;
    const uint32_t bColB = (uint32_t)(wn * 32) * 2;   // byte offset of warp's n range

    for (int i = 0; i < nk; i++) {
        if (i + 1 < nk) { CP_WAIT(1); } else { CP_WAIT(0); }
        __syncthreads();
        if (i + 2 < nk) load_stage(i + 2);

        const uint32_t stA = smem_base + (i % NSTAGE) * STAGEB;
        const uint32_t stB = stA + A_MATB;

        #pragma unroll
        for (int step = 0; step < 2; step++) {     // 32 k per step
            uint32_t ah[2][4][4];                  // [kc2][im][regs]
            uint32_t bf[4][4];                     // [nb][regs] (kc2*2 + 0/1)
            #pragma unroll
            for (int im = 0; im < 4; im++)
                #pragma unroll
                for (int kc2 = 0; kc2 < 2; kc2++)
                    ldsm_x4(ah[kc2][im][0], ah[kc2][im][1], ah[kc2][im][2], ah[kc2][im][3],
                            stA + (uint32_t)(aRow + im * 16) * A_ROWB + step * 64 + kc2 * 32 + aCS);
            #pragma unroll
            for (int nb = 0; nb < 4; nb++)
                ldsm_x4_trans(bf[nb][0], bf[nb][1], bf[nb][2], bf[nb][3],
                              stB + (uint32_t)(step * 32 + lane) * B_ROWB + bColB + nb * 16);
            #pragma unroll
            for (int kc2 = 0; kc2 < 2; kc2++)
                #pragma unroll
                for (int im = 0; im < 4; im++)
                    #pragma unroll
                    for (int nb = 0; nb < 4; nb++)
                        mma_f16(acc[im][nb][0], acc[im][nb][1], acc[im][nb][2], acc[im][nb][3],
                                ah[kc2][im][0], ah[kc2][im][1], ah[kc2][im][2], ah[kc2][im][3],
                                bf[nb][kc2 * 2], bf[nb][kc2 * 2 + 1]);
        }
    }

    #pragma unroll
    for (int im = 0; im < 4; im++) {
        int r = row0 + wm * 64 + im * 16 + arow;
        #pragma unroll
        for (int nb = 0; nb < 4; nb++) {
            int cc = col0 + wn * 32 + nb * 8 + acol;
            float2 b0 = *(const float2*)(bias + cc);
            float f0 = acc[im][nb][0] + b0.x;
            float f1 = acc[im][nb][1] + b0.y;
            float f2 = acc[im][nb][2] + b0.x;
            float f3 = acc[im][nb][3] + b0.y;
            if (OUT_HALF) {
                *(uint32_t*)(Ch + (size_t)r * N + cc)       = pack_h2(f0, f1);
                *(uint32_t*)(Ch + (size_t)(r + 8) * N + cc) = pack_h2(f2, f3);
            } else {
                *(float2*)(C + (size_t)r * N + cc)       = make_float2(f0, f1);
                *(float2*)(C + (size_t)(r + 8) * N + cc) = make_float2(f2, f3);
            }
        }
    }
}

// ---------------------------------------------------------------------------
// fp16 tensor-core causal flash attention. Heavy CTAs launch first.
// V loaded row-major straight from qkv; B-fragments built with ldmatrix.trans.
// Block 256 thr (8 warps x 16 q-rows = 128 q-rows). kv tiles of 64, double buf.
// ---------------------------------------------------------------------------
#define AT_ROWB 144                       // 64 fp16 = 128B + 16B pad
#define AT_QBYTES (128 * AT_ROWB)         // 18432
#define AT_TBY (64 * AT_ROWB)             // 9216
#define AT_STAGEB (2 * AT_TBY)            // K + V = 18432
#define AT_SMEM (AT_QBYTES + 2 * AT_STAGEB)   // 55296

__global__ __launch_bounds__(256, 2) void attn_mma_kernel(
    const __half* __restrict__ qkv, __half* __restrict__ out)
{
    extern __shared__ char sm[];
    const int tid  = threadIdx.x;
    const int lane = tid & 31;
    const int wid  = tid >> 5;
    const int qt = gridDim.x - 1 - blockIdx.x;   // heavy tiles first
    const int h = blockIdx.y, b = blockIdx.z;
    const int q0 = qt * 128;
    const uint32_t sb = smem_u32(sm);
    const int arow = lane >> 2;
    const int acol = lane & 3;
    const float SC2 = 0.18033688011f;   // 0.125 * log2(e)

    // ---- stage Q ----
    #pragma unroll
    for (int t = 0; t < 4; t++) {
        int c = tid + t * 256;
        int r = c >> 3, ch = c & 7;
        size_t g = (size_t)(b * L_ + q0 + r) * E_ + h * HD_ + ch * 8;
        CP_ASYNC16(sb + r * AT_ROWB + ch * 16, qkv + g);
    }
    CP_COMMIT();

    auto load_kv = [&](int t2) {
        const int k0 = t2 * 64;
        const uint32_t sbase = sb + AT_QBYTES + (t2 & 1) * AT_STAGEB;
        #pragma unroll
        for (int u = 0; u < 2; u++) {
            int c = tid + u * 256;
            int r = c >> 3, ch = c & 7;
            uint32_t so = r * AT_ROWB + ch * 16;
            size_t gk = (size_t)(b * L_ + k0 + r) * E_ + D_ + h * HD_ + ch * 8;
            CP_ASYNC16(sbase + so, qkv + gk);               // K rows
            CP_ASYNC16(sbase + AT_TBY + so, qkv + gk + D_); // V rows
        }
        CP_COMMIT();
    };

    load_kv(0);

    float o[8][4];
    #pragma unroll
    for (int i = 0; i < 8; i++)
        #pragma unroll
        for (int j = 0; j < 4; j++) o[i][j] = 0.f;
    float m0 = -1e30f, m1 = -1e30f, l0 = 0.f, l1 = 0.f;

    const int rg0 = q0 + wid * 16 + arow;
    const int rg1 = rg0 + 8;
    const int nt = 2 * qt + 2;

    const int nR  = lane & 7;
    const int kcS = (lane & 16) ? 32 : 0;
    const int cS  = (lane & 8) ? 16 : 0;
    const uint32_t vRowOff = (uint32_t)lane * AT_ROWB;

    uint32_t qf[4][4];
    bool qloaded = false;

    for (int t = 0; t < nt; t++) {
        CP_WAIT(0);
        __syncthreads();
        if (t + 1 < nt) load_kv(t + 1);

        if (!qloaded) {
            qloaded = true;
            const char* QH = sm;
            int r = wid * 16 + arow;
            #pragma unroll
            for (int kc = 0; kc < 4; kc++) {
                int colb = kc * 32 + acol * 4;
                qf[kc][0] = *(const uint32_t*)(QH + r * AT_ROWB + colb);
                qf[kc][1] = *(const uint32_t*)(QH + (r + 8) * AT_ROWB + colb);
                qf[kc][2] = *(const uint32_t*)(QH + r * AT_ROWB + colb + 16);
                qf[kc][3] = *(const uint32_t*)(QH + (r + 8) * AT_ROWB + colb + 16);
            }
        }

        const int k0 = t * 64;
        const uint32_t st = sb + AT_QBYTES + (t & 1) * AT_STAGEB;
        const uint32_t KH = st;
        const uint32_t VH = st + AT_TBY;

        const bool active = (k0 <= q0 + wid * 16 + 15);
        if (active) {
            // ---- S = Q @ K^T ----
            float s[8][4];
            #pragma unroll
            for (int i = 0; i < 8; i++)
                #pragma unroll
                for (int j = 0; j < 4; j++) s[i][j] = 0.f;

            #pragma unroll
            for (int nc = 0; nc < 8; nc++) {
                uint32_t rowOff = (uint32_t)(nc * 8 + nR) * AT_ROWB + cS + kcS;
                uint32_t bhf[4][2];
                ldsm_x4(bhf[0][0], bhf[0][1], bhf[1][0], bhf[1][1], KH + rowOff);
                ldsm_x4(bhf[2][0], bhf[2][1], bhf[3][0], bhf[3][1], KH + rowOff + 64);
                #pragma unroll
                for (int kc = 0; kc < 4; kc++)
                    mma_f16(s[nc][0], s[nc][1], s[nc][2], s[nc][3],
                            qf[kc][0], qf[kc][1], qf[kc][2], qf[kc][3],
                            bhf[kc][0], bhf[kc][1]);
            }

            // ---- causal mask ----
            if (k0 + 63 > q0 + wid * 16) {
                #pragma unroll
                for (int nc = 0; nc < 8; nc++) {
                    int kbase = k0 + nc * 8 + acol * 2;
                    #pragma unroll
                    for (int e = 0; e < 2; e++) {
                        if (kbase + e > rg0) s[nc][e]     = -1e30f;
                        if (kbase + e > rg1) s[nc][2 + e] = -1e30f;
                    }
                }
            }

            // ---- online softmax ----
            float tm0 = -1e30f, tm1 = -1e30f;
            #pragma unroll
            for (int nc = 0; nc < 8; nc++) {
                tm0 = fmaxf(tm0, fmaxf(s[nc][0], s[nc][1]));
                tm1 = fmaxf(tm1, fmaxf(s[nc][2], s[nc][3]));
            }
            tm0 = fmaxf(tm0, __shfl_xor_sync(0xffffffff, tm0, 1));
            tm0 = fmaxf(tm0, __shfl_xor_sync(0xffffffff, tm0, 2));
            tm1 = fmaxf(tm1, __shfl_xor_sync(0xffffffff, tm1, 1));
            tm1 = fmaxf(tm1, __shfl_xor_sync(0xffffffff, tm1, 2));

            float mn0 = fmaxf(m0, tm0);
            float mn1 = fmaxf(m1, tm1);
            float corr0 = exp2f((m0 - mn0) * SC2);
            float corr1 = exp2f((m1 - mn1) * SC2);

            float p[8][4];
            float rs0 = 0.f, rs1 = 0.f;
            #pragma unroll
            for (int nc = 0; nc < 8; nc++) {
                p[nc][0] = exp2f((s[nc][0] - mn0) * SC2);
                p[nc][1] = exp2f((s[nc][1] - mn0) * SC2);
                p[nc][2] = exp2f((s[nc][2] - mn1) * SC2);
                p[nc][3] = exp2f((s[nc][3] - mn1) * SC2);
                rs0 += p[nc][0] + p[nc][1];
                rs1 += p[nc][2] + p[nc][3];
            }
            rs0 += __shfl_xor_sync(0xffffffff, rs0, 1);
            rs0 += __shfl_xor_sync(0xffffffff, rs0, 2);
            rs1 += __shfl_xor_sync(0xffffffff, rs1, 1);
            rs1 += __shfl_xor_sync(0xffffffff, rs1, 2);

            l0 = l0 * corr0 + rs0;
            l1 = l1 * corr1 + rs1;
            m0 = mn0; m1 = mn1;
            #pragma unroll
            for (int nc = 0; nc < 8; nc++) {
                o[nc][0] *= corr0; o[nc][1] *= corr0;
                o[nc][2] *= corr1; o[nc][3] *= corr1;
            }

            // ---- pack P to fp16 A-fragments ----
            uint32_t pf[4][4];
            #pragma unroll
            for (int kc = 0; kc < 4; kc++) {
                const int n0c = 2 * kc, n1c = 2 * kc + 1;
                pf[kc][0] = pack_h2(p[n0c][0], p[n0c][1]);
                pf[kc][1] = pack_h2(p[n0c][2], p[n0c][3]);
                pf[kc][2] = pack_h2(p[n1c][0], p[n1c][1]);
                pf[kc][3] = pack_h2(p[n1c][2], p[n1c][3]);
            }

            // ---- O += P @ V (V via ldmatrix.trans, nc = d-block) ----
            #pragma unroll
            for (int nc = 0; nc < 8; nc++) {
                uint32_t vb[4][2];
                uint32_t base = VH + vRowOff + nc * 16;
                ldsm_x4_trans(vb[0][0], vb[0][1], vb[1][0], vb[1][1], base);
                ldsm_x4_trans(vb[2][0], vb[2][1], vb[3][0], vb[3][1], base + 32 * AT_ROWB);
                #pragma unroll
                for (int kc = 0; kc < 4; kc++)
                    mma_f16(o[nc][0], o[nc][1], o[nc][2], o[nc][3],
                            pf[kc][0], pf[kc][1], pf[kc][2], pf[kc][3],
                            vb[kc][0], vb[kc][1]);
            }
        }
    }

    // ---- epilogue ----
    const float inv0 = 1.f / l0;
    const float inv1 = 1.f / l1;
    const size_t tok0 = (size_t)(b * L_ + q0 + wid * 16 + arow);
    #pragma unroll
    for (int nc = 0; nc < 8; nc++) {
        int col = h * HD_ + nc * 8 + acol * 2;
        *(uint32_t*)(out + tok0 * D_ + col)       = pack_h2(o[nc][0] * inv0, o[nc][1] * inv0);
        *(uint32_t*)(out + (tok0 + 8) * D_ + col) = pack_h2(o[nc][2] * inv1, o[nc][3] * inv1);
    }
}

// ---------------------------------------------------------------------------
extern "C" void kernel_launch(void* const* d_in, const int* in_sizes, int n_in,
                              void* d_out, int out_size)
{
    const float* x     = (const float*)d_in[0];
    const float* w_in  = (const float*)d_in[1];
    const float* b_in  = (const float*)d_in[2];
    const float* w_out = (const float*)d_in[3];
    const float* b_out = (const float*)d_in[4];
    float* y = (float*)d_out;

    __half *qkv, *x16, *win16, *wout16, *att;
    cudaGetSymbolAddress((void**)&qkv,    g_qkv);
    cudaGetSymbolAddress((void**)&x16,    g_x16);
    cudaGetSymbolAddress((void**)&win16,  g_win16);
    cudaGetSymbolAddress((void**)&wout16, g_wout16);
    cudaGetSymbolAddress((void**)&att,    g_att);

    static bool attr_set = false;
    if (!attr_set) {
        cudaFuncSetAttribute(gemm_mma_kernel<true>,  cudaFuncAttributeMaxDynamicSharedMemorySize, SMEMB);
        cudaFuncSetAttribute(gemm_mma_kernel<false>, cudaFuncAttributeMaxDynamicSharedMemorySize, SMEMB);
        cudaFuncSetAttribute(attn_mma_kernel, cudaFuncAttributeMaxDynamicSharedMemorySize, AT_SMEM);
        attr_set = true;
    }

    // prep: fp32 -> fp16 converts (no transposes)
    convert_f16_kernel<<<(M_ * D_ / 4 + 255) / 256, 256>>>(x, x16, M_ * D_ / 4);
    convert_f16_kernel<<<(D_ * E_ / 4 + 255) / 256, 256>>>(w_in, win16, D_ * E_ / 4);
    convert_f16_kernel<<<(D_ * D_ / 4 + 255) / 256, 256>>>(w_out, wout16, D_ * D_ / 4);

    // 1) QKV projection -> fp16
    {
        dim3 grid(E_ / 128, M_ / 128);
        gemm_mma_kernel<true><<<grid, 256, SMEMB>>>(
            x16, win16, b_in, nullptr, qkv, M_, E_, D_);
    }

    // 2) tensor-core causal flash attention
    {
        dim3 grid(L_ / 128, H_, B_);
        attn_mma_kernel<<<grid, 256, AT_SMEM>>>(qkv, att);
    }

    // 3) output projection -> fp32 y
    {
        dim3 grid(D_ / 128, M_ / 128);
        gemm_mma_kernel<false><<<grid, 256, SMEMB>>>(
            att, wout16, b_out, y, nullptr, M_, D_, D_);
    }
}